// round 6
// baseline (speedup 1.0000x reference)
#include <cuda_runtime.h>
#include <cuda_pipeline.h>
#include <math.h>

#define B_   4
#define LQ_  2048
#define LK_  2048
#define XS_  1024
#define PD_  128

// Scratch for projected q/k/v (device globals: no allocation allowed).
// Values stored here are ALREADY rounded to TF32 (cvt.rna) so the attention
// kernel can cp.async them raw and the MMA truncation is lossless.
__device__ float g_q[B_ * LQ_ * PD_];
__device__ float g_k[B_ * LK_ * PD_];
__device__ float g_v[B_ * LK_ * PD_];

__device__ __forceinline__ float to_tf32(float x) {
    float r;
    asm("cvt.rna.tf32.f32 %0, %1;" : "=f"(r) : "f"(x));
    return r;
}

// D += A*B, m16n8k8 tf32. a: 4 regs, b: 2 regs, c: 4 fp32.
__device__ __forceinline__ void mma_tf32(float* c, const float* a, const float* b) {
    asm volatile(
        "mma.sync.aligned.m16n8k8.row.col.f32.tf32.tf32.f32 "
        "{%0,%1,%2,%3}, {%4,%5,%6,%7}, {%8,%9}, {%0,%1,%2,%3};\n"
        : "+f"(c[0]), "+f"(c[1]), "+f"(c[2]), "+f"(c[3])
        : "r"(__float_as_uint(a[0])), "r"(__float_as_uint(a[1])),
          "r"(__float_as_uint(a[2])), "r"(__float_as_uint(a[3])),
          "r"(__float_as_uint(b[0])), "r"(__float_as_uint(b[1])));
}

// ---------------------------------------------------------------------------
// Projection GEMM (tf32): C[8192,128] = A[8192,1024]@W[1024,128]+b
// Tile 64x128 (M halved vs R5 for wave balance: grid (128,3)=384 CTAs).
// 256 threads = 8 warps (4 m x 2 n), warp tile 16x64. BK=32.
// Load + smem patterns identical to the proven R3 code.
// ---------------------------------------------------------------------------
#define PA_PITCH 36
#define PW_PITCH 136

__global__ __launch_bounds__(256) void proj_kernel(
    const float* __restrict__ x, const float* __restrict__ y,
    const float* __restrict__ Wq, const float* __restrict__ bq,
    const float* __restrict__ Wk, const float* __restrict__ bk,
    const float* __restrict__ Wv, const float* __restrict__ bv)
{
    const float* A; const float* W; const float* bias; float* C;
    if (blockIdx.y == 0)      { A = x; W = Wq; bias = bq; C = g_q; }
    else if (blockIdx.y == 1) { A = y; W = Wk; bias = bk; C = g_k; }
    else                      { A = y; W = Wv; bias = bv; C = g_v; }

    __shared__ float As[64 * PA_PITCH];    // [m][k], BK=32 cols used
    __shared__ float Ws[32 * PW_PITCH];    // [k][n]

    const int tid  = threadIdx.x;
    const int wid  = tid >> 5;
    const int lane = tid & 31;
    const int lr = lane >> 2, lc = lane & 3;
    const int rw = (wid & 3) * 16;   // warp row base within tile
    const int cw = (wid >> 2) * 64;  // warp col base within tile
    const int row0 = blockIdx.x * 64;

    // A: 64 rows x 8 float4 along k (2/thread); W: 32 k-rows x 32 float4 (4/thread)
    float4 rA[2], rW[4];
    #pragma unroll
    for (int i = 0; i < 2; i++) {
        const int g = tid + i * 256;
        rA[i] = *(const float4*)(A + (size_t)(row0 + (g >> 3)) * XS_ + (g & 7) * 4);
    }
    #pragma unroll
    for (int i = 0; i < 4; i++) {
        const int g = tid + i * 256;
        rW[i] = *(const float4*)(W + (size_t)(g >> 5) * PD_ + (g & 31) * 4);
    }

    float acc[8][4];
    #pragma unroll
    for (int nf = 0; nf < 8; nf++)
        #pragma unroll
        for (int r = 0; r < 4; r++) acc[nf][r] = 0.0f;

    for (int c = 0; c < 32; c++) {
        __syncthreads();
        #pragma unroll
        for (int i = 0; i < 2; i++) {
            const int g = tid + i * 256;
            const int ar = g >> 3, ak = (g & 7) * 4;
            As[ar * PA_PITCH + ak + 0] = to_tf32(rA[i].x);
            As[ar * PA_PITCH + ak + 1] = to_tf32(rA[i].y);
            As[ar * PA_PITCH + ak + 2] = to_tf32(rA[i].z);
            As[ar * PA_PITCH + ak + 3] = to_tf32(rA[i].w);
        }
        #pragma unroll
        for (int i = 0; i < 4; i++) {
            const int g = tid + i * 256;
            const int wk = g >> 5, wn = (g & 31) * 4;
            Ws[wk * PW_PITCH + wn + 0] = to_tf32(rW[i].x);
            Ws[wk * PW_PITCH + wn + 1] = to_tf32(rW[i].y);
            Ws[wk * PW_PITCH + wn + 2] = to_tf32(rW[i].z);
            Ws[wk * PW_PITCH + wn + 3] = to_tf32(rW[i].w);
        }
        __syncthreads();

        if (c < 31) {
            const int k0 = (c + 1) * 32;
            #pragma unroll
            for (int i = 0; i < 2; i++) {
                const int g = tid + i * 256;
                rA[i] = *(const float4*)(A + (size_t)(row0 + (g >> 3)) * XS_ + k0 + (g & 7) * 4);
            }
            #pragma unroll
            for (int i = 0; i < 4; i++) {
                const int g = tid + i * 256;
                rW[i] = *(const float4*)(W + (size_t)(k0 + (g >> 5)) * PD_ + (g & 31) * 4);
            }
        }

        #pragma unroll
        for (int kf = 0; kf < 4; kf++) {
            const int k = kf * 8;
            float a[4];
            a[0] = As[(rw + lr) * PA_PITCH + k + lc];
            a[1] = As[(rw + lr + 8) * PA_PITCH + k + lc];
            a[2] = As[(rw + lr) * PA_PITCH + k + lc + 4];
            a[3] = As[(rw + lr + 8) * PA_PITCH + k + lc + 4];
            #pragma unroll
            for (int nf = 0; nf < 8; nf++) {
                float b[2];
                const int col = cw + nf * 8 + lr;
                b[0] = Ws[(k + lc) * PW_PITCH + col];
                b[1] = Ws[(k + lc + 4) * PW_PITCH + col];
                mma_tf32(acc[nf], a, b);
            }
        }
    }

    // Epilogue: +bias, round to tf32, store
    #pragma unroll
    for (int nf = 0; nf < 8; nf++) {
        const int row = row0 + rw + lr;
        const int col = cw + nf * 8 + 2 * lc;
        const float2 bb = *(const float2*)(bias + col);
        float2 o0, o1;
        o0.x = to_tf32(acc[nf][0] + bb.x);
        o0.y = to_tf32(acc[nf][1] + bb.y);
        o1.x = to_tf32(acc[nf][2] + bb.x);
        o1.y = to_tf32(acc[nf][3] + bb.y);
        *(float2*)(C + (size_t)row * PD_ + col) = o0;
        *(float2*)(C + (size_t)(row + 8) * PD_ + col) = o1;
    }
}

// ---------------------------------------------------------------------------
// Flash attention, tf32 mma, post-softmax triu(k=1) mask.
// grid (32, 4), 256 threads = 8 warps = 4(m) x 2(n):
//   warp (wm, wn): S quarter rows wm*16..+15, cols wn*32..+31;
//                  O half rows wm*16..+15, cols wn*64..+63.
// Softmax row stats combined across the 2 n-warps via smem (redm/redl).
// All pitches / fragment addressing identical to the proven R3 kernel.
// ---------------------------------------------------------------------------
#define BQ  64
#define BKT 64
#define QP  132
#define VP  136
#define PP  68
#define SMF_Q   0
#define SMF_K   (64 * QP)                      // 2 buffers of 64*132
#define SMF_V   (SMF_K + 2 * 64 * QP)          // 2 buffers of 64*136
#define SMF_P   (SMF_V + 2 * 64 * VP)
#define SMF_RED (SMF_P + 64 * PP)              // redm[2][64] + redl[2][64]
#define SMEM_FLOATS (SMF_RED + 256)
#define SMEM_BYTES  (SMEM_FLOATS * 4)

__global__ __launch_bounds__(256) void attn_kernel(const int* __restrict__ maskp,
                                                   float* __restrict__ out)
{
    extern __shared__ float sm[];
    float* Qs   = sm + SMF_Q;    // [r][d] pitch 132
    float* Ks   = sm + SMF_K;    // buf*[j][d] pitch 132
    float* Vs   = sm + SMF_V;    // buf*[j][d] pitch 136
    float* Ps   = sm + SMF_P;    // [r][j] pitch 68
    float* redm = sm + SMF_RED;       // [2][64] partial row max
    float* redl = sm + SMF_RED + 128; // [2][64] partial row sum

    const int b = blockIdx.y;
    const int qbase = blockIdx.x * BQ;
    const float* Qg = g_q + ((size_t)b * LQ_ + qbase) * PD_;
    const float* Kg = g_k + (size_t)b * LK_ * PD_;
    const float* Vg = g_v + (size_t)b * LK_ * PD_;

    const int tid  = threadIdx.x;
    const int wid  = tid >> 5;
    const int lane = tid & 31;
    const int lr = lane >> 2, lc = lane & 3;
    const int wm = wid & 3, wn = wid >> 2;
    const int r0w = wm * 16;   // warp's S/O row base
    const int c0w = wn * 32;   // warp's S col base
    const int d0w = wn * 64;   // warp's O col base
    const int msk = *maskp;
    const float SCALE = 0.0883883476483184f;  // 1/sqrt(128)

    // Prologue: async-copy Q + K/V tile 0 (8 float4 per array per thread)
    #pragma unroll
    for (int i = 0; i < 8; i++) {
        const int g = tid + i * 256;        // 2048 float4 per tile
        const int j = g >> 5, d4 = (g & 31) * 4;
        __pipeline_memcpy_async(&Qs[j * QP + d4], Qg + (size_t)j * PD_ + d4, 16);
        __pipeline_memcpy_async(&Ks[j * QP + d4], Kg + (size_t)j * PD_ + d4, 16);
        __pipeline_memcpy_async(&Vs[j * VP + d4], Vg + (size_t)j * PD_ + d4, 16);
    }
    __pipeline_commit();

    float oacc[8][4];
    #pragma unroll
    for (int nf = 0; nf < 8; nf++)
        #pragma unroll
        for (int r = 0; r < 4; r++) oacc[nf][r] = 0.0f;
    float m_run[2] = {-1e30f, -1e30f};
    float l_run[2] = {0.0f, 0.0f};

    for (int t = 0; t < LK_ / BKT; t++) {
        const int kbase = t * BKT;
        const int buf = t & 1;
        float* Kb = Ks + buf * 64 * QP;
        float* Vb = Vs + buf * 64 * VP;

        __pipeline_wait_prior(0);
        __syncthreads();   // K/V(t) ready; Ps/red reuse safe

        if (t + 1 < LK_ / BKT) {
            const int nb = (t + 1) & 1;
            float* Kn = Ks + nb * 64 * QP;
            float* Vn = Vs + nb * 64 * VP;
            const float* Kgs = Kg + (size_t)(kbase + BKT) * PD_;
            const float* Vgs = Vg + (size_t)(kbase + BKT) * PD_;
            #pragma unroll
            for (int i = 0; i < 8; i++) {
                const int g = tid + i * 256;
                const int j = g >> 5, d4 = (g & 31) * 4;
                __pipeline_memcpy_async(&Kn[j * QP + d4], Kgs + (size_t)j * PD_ + d4, 16);
                __pipeline_memcpy_async(&Vn[j * VP + d4], Vgs + (size_t)j * PD_ + d4, 16);
            }
            __pipeline_commit();
        }

        // ---- S quarter = Q[16 rows] @ K^T[32 cols] ----
        float sacc[4][4];
        #pragma unroll
        for (int nf = 0; nf < 4; nf++)
            #pragma unroll
            for (int r = 0; r < 4; r++) sacc[nf][r] = 0.0f;

        #pragma unroll 4
        for (int kf = 0; kf < 16; kf++) {
            const int k = kf * 8;
            float a[4];
            a[0] = Qs[(r0w + lr) * QP + k + lc];
            a[1] = Qs[(r0w + lr + 8) * QP + k + lc];
            a[2] = Qs[(r0w + lr) * QP + k + lc + 4];
            a[3] = Qs[(r0w + lr + 8) * QP + k + lc + 4];
            #pragma unroll
            for (int nf = 0; nf < 4; nf++) {
                float bfr[2];
                const int jcol = c0w + nf * 8 + lr;
                bfr[0] = Kb[jcol * QP + k + lc];
                bfr[1] = Kb[jcol * QP + k + lc + 4];
                mma_tf32(sacc[nf], a, bfr);
            }
        }
        #pragma unroll
        for (int nf = 0; nf < 4; nf++)
            #pragma unroll
            for (int r = 0; r < 4; r++) sacc[nf][r] *= SCALE;

        // partial row max over this warp's 32 cols (quad reduce over lc)
        float m_t[2] = {-1e30f, -1e30f};
        #pragma unroll
        for (int nf = 0; nf < 4; nf++) {
            m_t[0] = fmaxf(m_t[0], fmaxf(sacc[nf][0], sacc[nf][1]));
            m_t[1] = fmaxf(m_t[1], fmaxf(sacc[nf][2], sacc[nf][3]));
        }
        #pragma unroll
        for (int off = 2; off >= 1; off >>= 1) {
            m_t[0] = fmaxf(m_t[0], __shfl_xor_sync(0xffffffffu, m_t[0], off));
            m_t[1] = fmaxf(m_t[1], __shfl_xor_sync(0xffffffffu, m_t[1], off));
        }
        if (lc == 0) {
            redm[wn * 64 + r0w + lr]     = m_t[0];
            redm[wn * 64 + r0w + lr + 8] = m_t[1];
        }
        __syncthreads();

        float m_new[2], corr[2], lp[2] = {0.0f, 0.0f};
        {
            const int row = r0w + lr;
            m_new[0] = fmaxf(m_run[0], fmaxf(redm[row], redm[64 + row]));
            m_new[1] = fmaxf(m_run[1], fmaxf(redm[row + 8], redm[64 + row + 8]));
        }
        corr[0] = __expf(m_run[0] - m_new[0]);
        corr[1] = __expf(m_run[1] - m_new[1]);

        #pragma unroll
        for (int nf = 0; nf < 4; nf++) {
            #pragma unroll
            for (int r = 0; r < 4; r++) {
                const float e = __expf(sacc[nf][r] - m_new[r >> 1]);
                sacc[nf][r] = e;
                lp[r >> 1] += e;
            }
        }
        #pragma unroll
        for (int off = 2; off >= 1; off >>= 1) {
            lp[0] += __shfl_xor_sync(0xffffffffu, lp[0], off);
            lp[1] += __shfl_xor_sync(0xffffffffu, lp[1], off);
        }
        if (lc == 0) {
            redl[wn * 64 + r0w + lr]     = lp[0];
            redl[wn * 64 + r0w + lr + 8] = lp[1];
        }

        // Tile fully below/at diagonal for all rows of this CTA -> P == 0
        const bool pv_skip = msk && (kbase + BKT - 1 <= qbase);
        if (!pv_skip) {
            // masked P -> smem (tf32-rounded)
            const int rowg0 = qbase + r0w + lr;
            const int rowg1 = rowg0 + 8;
            #pragma unroll
            for (int nf = 0; nf < 4; nf++) {
                const int col = c0w + nf * 8 + 2 * lc;
                const int kidx = kbase + col;
                const bool z00 = msk && (kidx     <= rowg0);
                const bool z01 = msk && (kidx + 1 <= rowg0);
                const bool z10 = msk && (kidx     <= rowg1);
                const bool z11 = msk && (kidx + 1 <= rowg1);
                Ps[(r0w + lr) * PP + col]         = z00 ? 0.0f : to_tf32(sacc[nf][0]);
                Ps[(r0w + lr) * PP + col + 1]     = z01 ? 0.0f : to_tf32(sacc[nf][1]);
                Ps[(r0w + lr + 8) * PP + col]     = z10 ? 0.0f : to_tf32(sacc[nf][2]);
                Ps[(r0w + lr + 8) * PP + col + 1] = z11 ? 0.0f : to_tf32(sacc[nf][3]);
            }
        }
        __syncthreads();   // redl + Ps visible to all warps

        {
            const int row = r0w + lr;
            const float lt0 = redl[row] + redl[64 + row];
            const float lt1 = redl[row + 8] + redl[64 + row + 8];
            l_run[0] = l_run[0] * corr[0] + lt0;
            l_run[1] = l_run[1] * corr[1] + lt1;
            m_run[0] = m_new[0];
            m_run[1] = m_new[1];
        }
        #pragma unroll
        for (int nf = 0; nf < 8; nf++) {
            oacc[nf][0] *= corr[0]; oacc[nf][1] *= corr[0];
            oacc[nf][2] *= corr[1]; oacc[nf][3] *= corr[1];
        }

        if (!pv_skip) {
            // ---- O half += P[16 rows][64] @ V[64][64 cols] ----
            #pragma unroll 2
            for (int jf = 0; jf < 8; jf++) {
                const int j = jf * 8;
                float a[4];
                a[0] = Ps[(r0w + lr) * PP + j + lc];
                a[1] = Ps[(r0w + lr + 8) * PP + j + lc];
                a[2] = Ps[(r0w + lr) * PP + j + lc + 4];
                a[3] = Ps[(r0w + lr + 8) * PP + j + lc + 4];
                #pragma unroll
                for (int nf = 0; nf < 8; nf++) {
                    float bfr[2];
                    const int dcol = d0w + nf * 8 + lr;
                    bfr[0] = Vb[(j + lc) * VP + dcol];
                    bfr[1] = Vb[(j + lc + 4) * VP + dcol];
                    mma_tf32(oacc[nf], a, bfr);
                }
            }
        }
    }

    // Epilogue: normalize by full denominator, store
    float* Og = out + ((size_t)b * LQ_ + qbase) * PD_;
    const float inv0 = 1.0f / l_run[0];
    const float inv1 = 1.0f / l_run[1];
    #pragma unroll
    for (int nf = 0; nf < 8; nf++) {
        const int row = r0w + lr;
        const int col = d0w + nf * 8 + 2 * lc;
        float2 o0 = make_float2(oacc[nf][0] * inv0, oacc[nf][1] * inv0);
        float2 o1 = make_float2(oacc[nf][2] * inv1, oacc[nf][3] * inv1);
        *(float2*)(Og + (size_t)row * PD_ + col) = o0;
        *(float2*)(Og + (size_t)(row + 8) * PD_ + col) = o1;
    }
}

// ---------------------------------------------------------------------------
extern "C" void kernel_launch(void* const* d_in, const int* in_sizes, int n_in,
                              void* d_out, int out_size)
{
    const float* x  = (const float*)d_in[0];
    const float* y  = (const float*)d_in[1];
    const float* Wq = (const float*)d_in[2];
    const float* bq = (const float*)d_in[3];
    const float* Wk = (const float*)d_in[4];
    const float* bk = (const float*)d_in[5];
    const float* Wv = (const float*)d_in[6];
    const float* bv = (const float*)d_in[7];
    const int* maskp = (const int*)d_in[8];
    float* out = (float*)d_out;

    (void)in_sizes; (void)n_in; (void)out_size;

    cudaFuncSetAttribute(attn_kernel,
                         cudaFuncAttributeMaxDynamicSharedMemorySize, SMEM_BYTES);

    dim3 pg(128, 3);
    proj_kernel<<<pg, 256>>>(x, y, Wq, bq, Wk, bk, Wv, bv);

    dim3 ag(LQ_ / BQ, B_);
    attn_kernel<<<ag, 256, SMEM_BYTES>>>(maskp, out);
}

// round 7
// speedup vs baseline: 1.0143x; 1.0143x over previous
#include <cuda_runtime.h>
#include <cuda_pipeline.h>
#include <math.h>
#include <stdint.h>

#define B_   4
#define LQ_  2048
#define LK_  2048
#define XS_  1024
#define PD_  128

// Scratch for projected q/k/v (device globals: no allocation allowed).
// Values stored here are ALREADY rounded to TF32 (cvt.rna) so the attention
// kernel can cp.async them raw and the MMA truncation is lossless.
__device__ float g_q[B_ * LQ_ * PD_];
__device__ float g_k[B_ * LK_ * PD_];
__device__ float g_v[B_ * LK_ * PD_];

__device__ __forceinline__ float to_tf32(float x) {
    float r;
    asm("cvt.rna.tf32.f32 %0, %1;" : "=f"(r) : "f"(x));
    return r;
}

// D += A*B, m16n8k8 tf32. a: 4 regs, b: 2 regs, c: 4 fp32.
__device__ __forceinline__ void mma_tf32(float* c, const float* a, const float* b) {
    asm volatile(
        "mma.sync.aligned.m16n8k8.row.col.f32.tf32.tf32.f32 "
        "{%0,%1,%2,%3}, {%4,%5,%6,%7}, {%8,%9}, {%0,%1,%2,%3};\n"
        : "+f"(c[0]), "+f"(c[1]), "+f"(c[2]), "+f"(c[3])
        : "r"(__float_as_uint(a[0])), "r"(__float_as_uint(a[1])),
          "r"(__float_as_uint(a[2])), "r"(__float_as_uint(a[3])),
          "r"(__float_as_uint(b[0])), "r"(__float_as_uint(b[1])));
}

// Same, with raw tf32 bit patterns (for ldmatrix-sourced fragments).
__device__ __forceinline__ void mma_tf32u(float* c, const uint32_t* a, const uint32_t* b) {
    asm volatile(
        "mma.sync.aligned.m16n8k8.row.col.f32.tf32.tf32.f32 "
        "{%0,%1,%2,%3}, {%4,%5,%6,%7}, {%8,%9}, {%0,%1,%2,%3};\n"
        : "+f"(c[0]), "+f"(c[1]), "+f"(c[2]), "+f"(c[3])
        : "r"(a[0]), "r"(a[1]), "r"(a[2]), "r"(a[3]), "r"(b[0]), "r"(b[1]));
}

// ldmatrix x4: four 8x4-tf32 sub-tiles addressed as 8x8-b16 tiles.
__device__ __forceinline__ void ldsm4(uint32_t addr, uint32_t* r) {
    asm volatile("ldmatrix.sync.aligned.m8n8.x4.shared.b16 {%0,%1,%2,%3}, [%4];"
                 : "=r"(r[0]), "=r"(r[1]), "=r"(r[2]), "=r"(r[3])
                 : "r"(addr));
}

// ---------------------------------------------------------------------------
// Projection GEMM (tf32): C[8192,128] = A[8192,1024]@W[1024,128]+b
// Tile 64x128, grid (128,3)=384 CTAs (wave-balanced). 256 thr = 8 warps
// (4m x 2n), warp tile 16x64, BK=32. (R6 version — measured 64 us.)
// ---------------------------------------------------------------------------
#define PA_PITCH 36
#define PW_PITCH 136

__global__ __launch_bounds__(256) void proj_kernel(
    const float* __restrict__ x, const float* __restrict__ y,
    const float* __restrict__ Wq, const float* __restrict__ bq,
    const float* __restrict__ Wk, const float* __restrict__ bk,
    const float* __restrict__ Wv, const float* __restrict__ bv)
{
    const float* A; const float* W; const float* bias; float* C;
    if (blockIdx.y == 0)      { A = x; W = Wq; bias = bq; C = g_q; }
    else if (blockIdx.y == 1) { A = y; W = Wk; bias = bk; C = g_k; }
    else                      { A = y; W = Wv; bias = bv; C = g_v; }

    __shared__ float As[64 * PA_PITCH];    // [m][k], BK=32 cols used
    __shared__ float Ws[32 * PW_PITCH];    // [k][n]

    const int tid  = threadIdx.x;
    const int wid  = tid >> 5;
    const int lane = tid & 31;
    const int lr = lane >> 2, lc = lane & 3;
    const int rw = (wid & 3) * 16;   // warp row base within tile
    const int cw = (wid >> 2) * 64;  // warp col base within tile
    const int row0 = blockIdx.x * 64;

    float4 rA[2], rW[4];
    #pragma unroll
    for (int i = 0; i < 2; i++) {
        const int g = tid + i * 256;
        rA[i] = *(const float4*)(A + (size_t)(row0 + (g >> 3)) * XS_ + (g & 7) * 4);
    }
    #pragma unroll
    for (int i = 0; i < 4; i++) {
        const int g = tid + i * 256;
        rW[i] = *(const float4*)(W + (size_t)(g >> 5) * PD_ + (g & 31) * 4);
    }

    float acc[8][4];
    #pragma unroll
    for (int nf = 0; nf < 8; nf++)
        #pragma unroll
        for (int r = 0; r < 4; r++) acc[nf][r] = 0.0f;

    for (int c = 0; c < 32; c++) {
        __syncthreads();
        #pragma unroll
        for (int i = 0; i < 2; i++) {
            const int g = tid + i * 256;
            const int ar = g >> 3, ak = (g & 7) * 4;
            As[ar * PA_PITCH + ak + 0] = to_tf32(rA[i].x);
            As[ar * PA_PITCH + ak + 1] = to_tf32(rA[i].y);
            As[ar * PA_PITCH + ak + 2] = to_tf32(rA[i].z);
            As[ar * PA_PITCH + ak + 3] = to_tf32(rA[i].w);
        }
        #pragma unroll
        for (int i = 0; i < 4; i++) {
            const int g = tid + i * 256;
            const int wk = g >> 5, wn = (g & 31) * 4;
            Ws[wk * PW_PITCH + wn + 0] = to_tf32(rW[i].x);
            Ws[wk * PW_PITCH + wn + 1] = to_tf32(rW[i].y);
            Ws[wk * PW_PITCH + wn + 2] = to_tf32(rW[i].z);
            Ws[wk * PW_PITCH + wn + 3] = to_tf32(rW[i].w);
        }
        __syncthreads();

        if (c < 31) {
            const int k0 = (c + 1) * 32;
            #pragma unroll
            for (int i = 0; i < 2; i++) {
                const int g = tid + i * 256;
                rA[i] = *(const float4*)(A + (size_t)(row0 + (g >> 3)) * XS_ + k0 + (g & 7) * 4);
            }
            #pragma unroll
            for (int i = 0; i < 4; i++) {
                const int g = tid + i * 256;
                rW[i] = *(const float4*)(W + (size_t)(k0 + (g >> 5)) * PD_ + (g & 31) * 4);
            }
        }

        #pragma unroll
        for (int kf = 0; kf < 4; kf++) {
            const int k = kf * 8;
            float a[4];
            a[0] = As[(rw + lr) * PA_PITCH + k + lc];
            a[1] = As[(rw + lr + 8) * PA_PITCH + k + lc];
            a[2] = As[(rw + lr) * PA_PITCH + k + lc + 4];
            a[3] = As[(rw + lr + 8) * PA_PITCH + k + lc + 4];
            #pragma unroll
            for (int nf = 0; nf < 8; nf++) {
                float b[2];
                const int col = cw + nf * 8 + lr;
                b[0] = Ws[(k + lc) * PW_PITCH + col];
                b[1] = Ws[(k + lc + 4) * PW_PITCH + col];
                mma_tf32(acc[nf], a, b);
            }
        }
    }

    #pragma unroll
    for (int nf = 0; nf < 8; nf++) {
        const int row = row0 + rw + lr;
        const int col = cw + nf * 8 + 2 * lc;
        const float2 bb = *(const float2*)(bias + col);
        float2 o0, o1;
        o0.x = to_tf32(acc[nf][0] + bb.x);
        o0.y = to_tf32(acc[nf][1] + bb.y);
        o1.x = to_tf32(acc[nf][2] + bb.x);
        o1.y = to_tf32(acc[nf][3] + bb.y);
        *(float2*)(C + (size_t)row * PD_ + col) = o0;
        *(float2*)(C + (size_t)(row + 8) * PD_ + col) = o1;
    }
}

// ---------------------------------------------------------------------------
// Flash attention, tf32 mma + ldmatrix fragments, post-softmax triu(k=1) mask.
// R3 structure (grid (32,4), 128 thr = 4 warps, warp owns 16 S-rows) with
// scalar fragment LDS replaced by ldmatrix.x4. V is transposed per tile into
// Vt[d][j] (cooperative smem->smem pass) so its B-frags are LDSM too; the V
// double buffer is dropped to pay for Vt (total smem unchanged: 188416 B).
// ---------------------------------------------------------------------------
#define BQ  64
#define BKT 64
#define QP  132
#define VP  136
#define VTP 68
#define PP  68
#define SMF_Q  0
#define SMF_K  (64 * QP)                 // 2 buffers of 64*132
#define SMF_V  (SMF_K + 2 * 64 * QP)     // 1 buffer [j][d] pitch 136
#define SMF_VT (SMF_V + 64 * VP)         // [d][j] pitch 68
#define SMF_P  (SMF_VT + 128 * VTP)
#define SMEM_FLOATS (SMF_P + 64 * PP)    // 47104 floats = 188416 B
#define SMEM_BYTES  (SMEM_FLOATS * 4)
#define NT (LK_ / BKT)

__global__ __launch_bounds__(128) void attn_kernel(const int* __restrict__ maskp,
                                                   float* __restrict__ out)
{
    extern __shared__ float sm[];
    float* Qs = sm + SMF_Q;    // [r][d] pitch 132
    float* Ks = sm + SMF_K;    // buf*[j][d] pitch 132
    float* Vs = sm + SMF_V;    // [j][d] pitch 136
    float* Vt = sm + SMF_VT;   // [d][j] pitch 68
    float* Ps = sm + SMF_P;    // [r][j] pitch 68

    const int b = blockIdx.y;
    const int qbase = blockIdx.x * BQ;
    const float* Qg = g_q + ((size_t)b * LQ_ + qbase) * PD_;
    const float* Kg = g_k + (size_t)b * LK_ * PD_;
    const float* Vg = g_v + (size_t)b * LK_ * PD_;

    const int tid  = threadIdx.x;
    const int wid  = tid >> 5;
    const int lane = tid & 31;
    const int lr = lane >> 2, lc = lane & 3;
    const int g8 = lane >> 3, r8 = lane & 7;
    const int r0w = wid * 16;              // warp's S-row base
    const int msk = *maskp;
    const float SCALE = 0.0883883476483184f;  // 1/sqrt(128)

    const uint32_t qs_u = (uint32_t)__cvta_generic_to_shared(Qs);
    const uint32_t ks_u = (uint32_t)__cvta_generic_to_shared(Ks);
    const uint32_t vt_u = (uint32_t)__cvta_generic_to_shared(Vt);
    const uint32_t ps_u = (uint32_t)__cvta_generic_to_shared(Ps);

    // LDSM per-thread base offsets (float elements).
    // A-frag (Q/P): tiles (rows +0/+8, col-chunks 0/4) -> regs a0..a3.
    // B-frag (K/Vt): tiles (rows +0..7/+8..15, col-chunks 0/4) -> {b0,b1} x2 nf.
    const int q_off = (r0w + (g8 & 1) * 8 + r8) * QP + (g8 >> 1) * 4;
    const int k_off = ((g8 >> 1) * 8 + r8) * QP + (g8 & 1) * 4;
    const int p_off = (r0w + (g8 & 1) * 8 + r8) * PP + (g8 >> 1) * 4;
    const int v_off = ((g8 >> 1) * 8 + r8) * VTP + (g8 & 1) * 4;

    // Prologue: async-copy Q + K tile 0 + V tile 0
    #pragma unroll
    for (int i = 0; i < 16; i++) {
        const int g = tid + i * 128;       // 2048 float4 per tile
        const int j = g >> 5, d4 = (g & 31) * 4;
        __pipeline_memcpy_async(&Qs[j * QP + d4], Qg + (size_t)j * PD_ + d4, 16);
        __pipeline_memcpy_async(&Ks[j * QP + d4], Kg + (size_t)j * PD_ + d4, 16);
        __pipeline_memcpy_async(&Vs[j * VP + d4], Vg + (size_t)j * PD_ + d4, 16);
    }
    __pipeline_commit();

    float oacc[16][4];
    #pragma unroll
    for (int nf = 0; nf < 16; nf++)
        #pragma unroll
        for (int r = 0; r < 4; r++) oacc[nf][r] = 0.0f;
    float m_run[2] = {-1e30f, -1e30f};
    float l_run[2] = {0.0f, 0.0f};

    for (int t = 0; t < NT; t++) {
        const int kbase = t * BKT;
        const uint32_t kb_u = ks_u + (uint32_t)(t & 1) * (64 * QP * 4);
        const bool pv_skip = msk && (kbase + BKT - 1 <= qbase);

        __pipeline_wait_prior(0);
        __syncthreads();   // K(t)/V(t) landed; prior tile's PV (reads Vt) done

        // Prefetch K(t+1) into the other K buffer.
        if (t + 1 < NT) {
            float* Kn = Ks + ((t + 1) & 1) * (64 * QP);
            const float* Kgs = Kg + (size_t)(kbase + BKT) * PD_;
            #pragma unroll
            for (int i = 0; i < 16; i++) {
                const int g = tid + i * 128;
                const int j = g >> 5, d4 = (g & 31) * 4;
                __pipeline_memcpy_async(&Kn[j * QP + d4], Kgs + (size_t)j * PD_ + d4, 16);
            }
            __pipeline_commit();
        }

        // Transpose V(t): Vs[j][d] -> Vt[d][j] (skip if PV will be skipped).
        if (!pv_skip) {
            const int jj = tid & 63;
            const int dh = (tid >> 6) << 4;   // float4 chunk base: 0 or 16
            #pragma unroll
            for (int i = 0; i < 16; i++) {
                const float4 v = *(const float4*)&Vs[jj * VP + (dh + i) * 4];
                const int d0 = (dh + i) * 4;
                Vt[(d0 + 0) * VTP + jj] = v.x;
                Vt[(d0 + 1) * VTP + jj] = v.y;
                Vt[(d0 + 2) * VTP + jj] = v.z;
                Vt[(d0 + 3) * VTP + jj] = v.w;
            }
        }
        __syncthreads();   // Vt complete; Vs free for overwrite

        // Prefetch V(t+1) into Vs (single buffer; consumed only at next tile top).
        if (t + 1 < NT) {
            const float* Vgs = Vg + (size_t)(kbase + BKT) * PD_;
            #pragma unroll
            for (int i = 0; i < 16; i++) {
                const int g = tid + i * 128;
                const int j = g >> 5, d4 = (g & 31) * 4;
                __pipeline_memcpy_async(&Vs[j * VP + d4], Vgs + (size_t)j * PD_ + d4, 16);
            }
            __pipeline_commit();
        }

        // ---- S = Q @ K^T (each warp: 16 rows x 64 cols) ----
        float sacc[8][4];
        #pragma unroll
        for (int nf = 0; nf < 8; nf++)
            #pragma unroll
            for (int r = 0; r < 4; r++) sacc[nf][r] = 0.0f;

        #pragma unroll 4
        for (int kf = 0; kf < 16; kf++) {
            uint32_t qa[4];
            ldsm4(qs_u + (uint32_t)(q_off + kf * 8) * 4, qa);
            #pragma unroll
            for (int nfp = 0; nfp < 4; nfp++) {
                uint32_t kb[4];
                ldsm4(kb_u + (uint32_t)(k_off + nfp * 16 * QP + kf * 8) * 4, kb);
                mma_tf32u(sacc[2 * nfp],     qa, kb);
                mma_tf32u(sacc[2 * nfp + 1], qa, kb + 2);
            }
        }

        // ---- online softmax (warp-local; rows lr and lr+8 of this warp) ----
        #pragma unroll
        for (int nf = 0; nf < 8; nf++)
            #pragma unroll
            for (int r = 0; r < 4; r++) sacc[nf][r] *= SCALE;

        float m_t[2] = {-1e30f, -1e30f};
        #pragma unroll
        for (int nf = 0; nf < 8; nf++) {
            m_t[0] = fmaxf(m_t[0], fmaxf(sacc[nf][0], sacc[nf][1]));
            m_t[1] = fmaxf(m_t[1], fmaxf(sacc[nf][2], sacc[nf][3]));
        }
        #pragma unroll
        for (int off = 2; off >= 1; off >>= 1) {
            m_t[0] = fmaxf(m_t[0], __shfl_xor_sync(0xffffffffu, m_t[0], off));
            m_t[1] = fmaxf(m_t[1], __shfl_xor_sync(0xffffffffu, m_t[1], off));
        }
        float m_new[2], corr[2], lp[2] = {0.0f, 0.0f};
        #pragma unroll
        for (int r = 0; r < 2; r++) {
            m_new[r] = fmaxf(m_run[r], m_t[r]);
            corr[r] = __expf(m_run[r] - m_new[r]);
        }
        #pragma unroll
        for (int nf = 0; nf < 8; nf++) {
            #pragma unroll
            for (int r = 0; r < 4; r++) {
                const float e = __expf(sacc[nf][r] - m_new[r >> 1]);
                sacc[nf][r] = e;
                lp[r >> 1] += e;
            }
        }
        #pragma unroll
        for (int off = 2; off >= 1; off >>= 1) {
            lp[0] += __shfl_xor_sync(0xffffffffu, lp[0], off);
            lp[1] += __shfl_xor_sync(0xffffffffu, lp[1], off);
        }
        #pragma unroll
        for (int r = 0; r < 2; r++) {
            l_run[r] = l_run[r] * corr[r] + lp[r];
            m_run[r] = m_new[r];
        }
        #pragma unroll
        for (int nf = 0; nf < 16; nf++) {
            oacc[nf][0] *= corr[0]; oacc[nf][1] *= corr[0];
            oacc[nf][2] *= corr[1]; oacc[nf][3] *= corr[1];
        }

        if (!pv_skip) {
            // masked P -> smem (tf32-rounded)
            const int rowg0 = qbase + r0w + lr;
            const int rowg1 = rowg0 + 8;
            #pragma unroll
            for (int nf = 0; nf < 8; nf++) {
                const int col = nf * 8 + 2 * lc;
                const int kidx = kbase + col;
                const bool z00 = msk && (kidx     <= rowg0);
                const bool z01 = msk && (kidx + 1 <= rowg0);
                const bool z10 = msk && (kidx     <= rowg1);
                const bool z11 = msk && (kidx + 1 <= rowg1);
                Ps[(r0w + lr) * PP + col]         = z00 ? 0.0f : to_tf32(sacc[nf][0]);
                Ps[(r0w + lr) * PP + col + 1]     = z01 ? 0.0f : to_tf32(sacc[nf][1]);
                Ps[(r0w + lr + 8) * PP + col]     = z10 ? 0.0f : to_tf32(sacc[nf][2]);
                Ps[(r0w + lr + 8) * PP + col + 1] = z11 ? 0.0f : to_tf32(sacc[nf][3]);
            }
            __syncwarp();

            // ---- O += P @ V (ldmatrix A-frag from Ps, B-frag from Vt) ----
            #pragma unroll 2
            for (int jf = 0; jf < 8; jf++) {
                uint32_t pa[4];
                ldsm4(ps_u + (uint32_t)(p_off + jf * 8) * 4, pa);
                #pragma unroll
                for (int nfp = 0; nfp < 8; nfp++) {
                    uint32_t vb[4];
                    ldsm4(vt_u + (uint32_t)(v_off + nfp * 16 * VTP + jf * 8) * 4, vb);
                    mma_tf32u(oacc[2 * nfp],     pa, vb);
                    mma_tf32u(oacc[2 * nfp + 1], pa, vb + 2);
                }
            }
            __syncwarp();
        }
    }

    // Epilogue: normalize by full denominator, store
    float* Og = out + ((size_t)b * LQ_ + qbase) * PD_;
    const float inv0 = 1.0f / l_run[0];
    const float inv1 = 1.0f / l_run[1];
    #pragma unroll
    for (int nf = 0; nf < 16; nf++) {
        const int row = r0w + lr;
        const int col = nf * 8 + 2 * lc;
        float2 o0 = make_float2(oacc[nf][0] * inv0, oacc[nf][1] * inv0);
        float2 o1 = make_float2(oacc[nf][2] * inv1, oacc[nf][3] * inv1);
        *(float2*)(Og + (size_t)row * PD_ + col) = o0;
        *(float2*)(Og + (size_t)(row + 8) * PD_ + col) = o1;
    }
}

// ---------------------------------------------------------------------------
extern "C" void kernel_launch(void* const* d_in, const int* in_sizes, int n_in,
                              void* d_out, int out_size)
{
    const float* x  = (const float*)d_in[0];
    const float* y  = (const float*)d_in[1];
    const float* Wq = (const float*)d_in[2];
    const float* bq = (const float*)d_in[3];
    const float* Wk = (const float*)d_in[4];
    const float* bk = (const float*)d_in[5];
    const float* Wv = (const float*)d_in[6];
    const float* bv = (const float*)d_in[7];
    const int* maskp = (const int*)d_in[8];
    float* out = (float*)d_out;

    (void)in_sizes; (void)n_in; (void)out_size;

    cudaFuncSetAttribute(attn_kernel,
                         cudaFuncAttributeMaxDynamicSharedMemorySize, SMEM_BYTES);

    dim3 pg(128, 3);
    proj_kernel<<<pg, 256>>>(x, y, Wq, bq, Wk, bk, Wv, bv);

    dim3 ag(LQ_ / BQ, B_);
    attn_kernel<<<ag, 128, SMEM_BYTES>>>(maskp, out);
}

// round 8
// speedup vs baseline: 1.1463x; 1.1301x over previous
#include <cuda_runtime.h>
#include <cuda_pipeline.h>
#include <math.h>

#define B_   4
#define LQ_  2048
#define LK_  2048
#define XS_  1024
#define PD_  128
#define NSPLIT 2

// Scratch (device globals: no allocation allowed). g_q/k/v hold TF32-rounded
// projections; g_po/g_ml hold split-KV partial outputs.
__device__ float g_q[B_ * LQ_ * PD_];
__device__ float g_k[B_ * LK_ * PD_];
__device__ float g_v[B_ * LK_ * PD_];
__device__ float g_po[NSPLIT * B_ * LQ_ * PD_];
__device__ float g_ml[NSPLIT * B_ * LQ_ * 2];

__device__ __forceinline__ float to_tf32(float x) {
    float r;
    asm("cvt.rna.tf32.f32 %0, %1;" : "=f"(r) : "f"(x));
    return r;
}

// D += A*B, m16n8k8 tf32. a: 4 regs, b: 2 regs, c: 4 fp32.
__device__ __forceinline__ void mma_tf32(float* c, const float* a, const float* b) {
    asm volatile(
        "mma.sync.aligned.m16n8k8.row.col.f32.tf32.tf32.f32 "
        "{%0,%1,%2,%3}, {%4,%5,%6,%7}, {%8,%9}, {%0,%1,%2,%3};\n"
        : "+f"(c[0]), "+f"(c[1]), "+f"(c[2]), "+f"(c[3])
        : "r"(__float_as_uint(a[0])), "r"(__float_as_uint(a[1])),
          "r"(__float_as_uint(a[2])), "r"(__float_as_uint(a[3])),
          "r"(__float_as_uint(b[0])), "r"(__float_as_uint(b[1])));
}

// ---------------------------------------------------------------------------
// Projection GEMM (tf32): C[8192,128] = A[8192,1024]@W[1024,128]+b
// Tile 64x128, grid (128,3)=384 CTAs (wave-balanced). 256 thr = 8 warps
// (4m x 2n), warp tile 16x64, BK=32. (R6 version — measured 64 us.)
// ---------------------------------------------------------------------------
#define PA_PITCH 36
#define PW_PITCH 136

__global__ __launch_bounds__(256) void proj_kernel(
    const float* __restrict__ x, const float* __restrict__ y,
    const float* __restrict__ Wq, const float* __restrict__ bq,
    const float* __restrict__ Wk, const float* __restrict__ bk,
    const float* __restrict__ Wv, const float* __restrict__ bv)
{
    const float* A; const float* W; const float* bias; float* C;
    if (blockIdx.y == 0)      { A = x; W = Wq; bias = bq; C = g_q; }
    else if (blockIdx.y == 1) { A = y; W = Wk; bias = bk; C = g_k; }
    else                      { A = y; W = Wv; bias = bv; C = g_v; }

    __shared__ float As[64 * PA_PITCH];    // [m][k], BK=32 cols used
    __shared__ float Ws[32 * PW_PITCH];    // [k][n]

    const int tid  = threadIdx.x;
    const int wid  = tid >> 5;
    const int lane = tid & 31;
    const int lr = lane >> 2, lc = lane & 3;
    const int rw = (wid & 3) * 16;   // warp row base within tile
    const int cw = (wid >> 2) * 64;  // warp col base within tile
    const int row0 = blockIdx.x * 64;

    float4 rA[2], rW[4];
    #pragma unroll
    for (int i = 0; i < 2; i++) {
        const int g = tid + i * 256;
        rA[i] = *(const float4*)(A + (size_t)(row0 + (g >> 3)) * XS_ + (g & 7) * 4);
    }
    #pragma unroll
    for (int i = 0; i < 4; i++) {
        const int g = tid + i * 256;
        rW[i] = *(const float4*)(W + (size_t)(g >> 5) * PD_ + (g & 31) * 4);
    }

    float acc[8][4];
    #pragma unroll
    for (int nf = 0; nf < 8; nf++)
        #pragma unroll
        for (int r = 0; r < 4; r++) acc[nf][r] = 0.0f;

    for (int c = 0; c < 32; c++) {
        __syncthreads();
        #pragma unroll
        for (int i = 0; i < 2; i++) {
            const int g = tid + i * 256;
            const int ar = g >> 3, ak = (g & 7) * 4;
            As[ar * PA_PITCH + ak + 0] = to_tf32(rA[i].x);
            As[ar * PA_PITCH + ak + 1] = to_tf32(rA[i].y);
            As[ar * PA_PITCH + ak + 2] = to_tf32(rA[i].z);
            As[ar * PA_PITCH + ak + 3] = to_tf32(rA[i].w);
        }
        #pragma unroll
        for (int i = 0; i < 4; i++) {
            const int g = tid + i * 256;
            const int wk = g >> 5, wn = (g & 31) * 4;
            Ws[wk * PW_PITCH + wn + 0] = to_tf32(rW[i].x);
            Ws[wk * PW_PITCH + wn + 1] = to_tf32(rW[i].y);
            Ws[wk * PW_PITCH + wn + 2] = to_tf32(rW[i].z);
            Ws[wk * PW_PITCH + wn + 3] = to_tf32(rW[i].w);
        }
        __syncthreads();

        if (c < 31) {
            const int k0 = (c + 1) * 32;
            #pragma unroll
            for (int i = 0; i < 2; i++) {
                const int g = tid + i * 256;
                rA[i] = *(const float4*)(A + (size_t)(row0 + (g >> 3)) * XS_ + k0 + (g & 7) * 4);
            }
            #pragma unroll
            for (int i = 0; i < 4; i++) {
                const int g = tid + i * 256;
                rW[i] = *(const float4*)(W + (size_t)(k0 + (g >> 5)) * PD_ + (g & 31) * 4);
            }
        }

        #pragma unroll
        for (int kf = 0; kf < 4; kf++) {
            const int k = kf * 8;
            float a[4];
            a[0] = As[(rw + lr) * PA_PITCH + k + lc];
            a[1] = As[(rw + lr + 8) * PA_PITCH + k + lc];
            a[2] = As[(rw + lr) * PA_PITCH + k + lc + 4];
            a[3] = As[(rw + lr + 8) * PA_PITCH + k + lc + 4];
            #pragma unroll
            for (int nf = 0; nf < 8; nf++) {
                float b[2];
                const int col = cw + nf * 8 + lr;
                b[0] = Ws[(k + lc) * PW_PITCH + col];
                b[1] = Ws[(k + lc + 4) * PW_PITCH + col];
                mma_tf32(acc[nf], a, b);
            }
        }
    }

    #pragma unroll
    for (int nf = 0; nf < 8; nf++) {
        const int row = row0 + rw + lr;
        const int col = cw + nf * 8 + 2 * lc;
        const float2 bb = *(const float2*)(bias + col);
        float2 o0, o1;
        o0.x = to_tf32(acc[nf][0] + bb.x);
        o0.y = to_tf32(acc[nf][1] + bb.y);
        o1.x = to_tf32(acc[nf][2] + bb.x);
        o1.y = to_tf32(acc[nf][3] + bb.y);
        *(float2*)(C + (size_t)row * PD_ + col) = o0;
        *(float2*)(C + (size_t)(row + 8) * PD_ + col) = o1;
    }
}

// ---------------------------------------------------------------------------
// Flash attention, tf32 mma, post-softmax triu(k=1) mask.  Split-KV x2.
// grid (32, 4, 2), 128 threads = 4 warps; each warp owns 16 full S-rows
// (exact R3 structure). BKT=32 so smem = 111,616 B -> 2 CTAs/SM; the two
// resident CTAs interleave LDS/MMA/MUFU with no added synchronization.
// Each split covers 1024 keys (32 tiles); emits unnormalized partial O +
// per-row (m, l), merged exactly by combine_kernel.
// ---------------------------------------------------------------------------
#define BQ  64
#define BKT 32
#define NT  (LK_ / BKT / NSPLIT)   // 32 tiles per split
#define QP  132
#define VP  136
#define PP  36
#define SMF_Q  0
#define SMF_K  (64 * QP)                       // 2 buffers of 32*132
#define SMF_V  (SMF_K + 2 * BKT * QP)          // 2 buffers of 32*136
#define SMF_P  (SMF_V + 2 * BKT * VP)
#define SMEM_FLOATS (SMF_P + 64 * PP)          // 27904 floats
#define SMEM_BYTES  (SMEM_FLOATS * 4)          // 111,616 B

__global__ __launch_bounds__(128) void attn_kernel(const int* __restrict__ maskp)
{
    extern __shared__ float sm[];
    float* Qs = sm + SMF_Q;   // [r][d] pitch 132
    float* Ks = sm + SMF_K;   // buf*[j][d] pitch 132 (32 rows)
    float* Vs = sm + SMF_V;   // buf*[j][d] pitch 136 (32 rows)
    float* Ps = sm + SMF_P;   // [r][j] pitch 36 (64 rows x 32 cols)

    const int b = blockIdx.y;
    const int qbase = blockIdx.x * BQ;
    const int split = blockIdx.z;
    const int kstart = split * (LK_ / NSPLIT);

    const float* Qg = g_q + ((size_t)b * LQ_ + qbase) * PD_;
    const float* Kg = g_k + (size_t)b * LK_ * PD_;
    const float* Vg = g_v + (size_t)b * LK_ * PD_;

    const int tid  = threadIdx.x;
    const int wid  = tid >> 5;
    const int lane = tid & 31;
    const int lr = lane >> 2, lc = lane & 3;
    const int r0w = wid * 16;              // warp's S-row base
    const int msk = *maskp;
    const float SCALE = 0.0883883476483184f;  // 1/sqrt(128)

    // Prologue: async-copy Q + K/V tile 0 of this split (one commit group)
    #pragma unroll
    for (int i = 0; i < 16; i++) {
        const int g = tid + i * 128;       // Q: 2048 float4
        const int j = g >> 5, d4 = (g & 31) * 4;
        __pipeline_memcpy_async(&Qs[j * QP + d4], Qg + (size_t)j * PD_ + d4, 16);
    }
    #pragma unroll
    for (int i = 0; i < 8; i++) {
        const int g = tid + i * 128;       // K/V: 1024 float4 each
        const int j = g >> 5, d4 = (g & 31) * 4;
        __pipeline_memcpy_async(&Ks[j * QP + d4],
                                Kg + (size_t)(kstart + j) * PD_ + d4, 16);
        __pipeline_memcpy_async(&Vs[j * VP + d4],
                                Vg + (size_t)(kstart + j) * PD_ + d4, 16);
    }
    __pipeline_commit();

    float oacc[16][4];
    #pragma unroll
    for (int nf = 0; nf < 16; nf++)
        #pragma unroll
        for (int r = 0; r < 4; r++) oacc[nf][r] = 0.0f;
    float m_run[2] = {-1e30f, -1e30f};
    float l_run[2] = {0.0f, 0.0f};

    for (int t = 0; t < NT; t++) {
        const int kbase = kstart + t * BKT;
        const int buf = t & 1;
        float* Kb = Ks + buf * BKT * QP;
        float* Vb = Vs + buf * BKT * VP;

        __pipeline_wait_prior(0);
        __syncthreads();

        if (t + 1 < NT) {
            const int nb = (t + 1) & 1;
            float* Kn = Ks + nb * BKT * QP;
            float* Vn = Vs + nb * BKT * VP;
            const float* Kgs = Kg + (size_t)(kbase + BKT) * PD_;
            const float* Vgs = Vg + (size_t)(kbase + BKT) * PD_;
            #pragma unroll
            for (int i = 0; i < 8; i++) {
                const int g = tid + i * 128;
                const int j = g >> 5, d4 = (g & 31) * 4;
                __pipeline_memcpy_async(&Kn[j * QP + d4], Kgs + (size_t)j * PD_ + d4, 16);
                __pipeline_memcpy_async(&Vn[j * VP + d4], Vgs + (size_t)j * PD_ + d4, 16);
            }
            __pipeline_commit();
        }

        // ---- S = Q @ K^T (each warp: 16 rows x 32 cols) ----
        float sacc[4][4];
        #pragma unroll
        for (int nf = 0; nf < 4; nf++)
            #pragma unroll
            for (int r = 0; r < 4; r++) sacc[nf][r] = 0.0f;

        #pragma unroll 4
        for (int kf = 0; kf < 16; kf++) {
            const int k = kf * 8;
            float a[4];
            a[0] = Qs[(r0w + lr) * QP + k + lc];
            a[1] = Qs[(r0w + lr + 8) * QP + k + lc];
            a[2] = Qs[(r0w + lr) * QP + k + lc + 4];
            a[3] = Qs[(r0w + lr + 8) * QP + k + lc + 4];
            #pragma unroll
            for (int nf = 0; nf < 4; nf++) {
                float bfr[2];
                bfr[0] = Kb[(nf * 8 + lr) * QP + k + lc];
                bfr[1] = Kb[(nf * 8 + lr) * QP + k + lc + 4];
                mma_tf32(sacc[nf], a, bfr);
            }
        }

        // ---- online softmax (warp-local; rows lr and lr+8 of this warp) ----
        #pragma unroll
        for (int nf = 0; nf < 4; nf++)
            #pragma unroll
            for (int r = 0; r < 4; r++) sacc[nf][r] *= SCALE;

        float m_t[2] = {-1e30f, -1e30f};
        #pragma unroll
        for (int nf = 0; nf < 4; nf++) {
            m_t[0] = fmaxf(m_t[0], fmaxf(sacc[nf][0], sacc[nf][1]));
            m_t[1] = fmaxf(m_t[1], fmaxf(sacc[nf][2], sacc[nf][3]));
        }
        #pragma unroll
        for (int off = 2; off >= 1; off >>= 1) {
            m_t[0] = fmaxf(m_t[0], __shfl_xor_sync(0xffffffffu, m_t[0], off));
            m_t[1] = fmaxf(m_t[1], __shfl_xor_sync(0xffffffffu, m_t[1], off));
        }
        float m_new[2], corr[2], lp[2] = {0.0f, 0.0f};
        #pragma unroll
        for (int r = 0; r < 2; r++) {
            m_new[r] = fmaxf(m_run[r], m_t[r]);
            corr[r] = __expf(m_run[r] - m_new[r]);
        }
        #pragma unroll
        for (int nf = 0; nf < 4; nf++) {
            #pragma unroll
            for (int r = 0; r < 4; r++) {
                const float e = __expf(sacc[nf][r] - m_new[r >> 1]);
                sacc[nf][r] = e;
                lp[r >> 1] += e;
            }
        }
        #pragma unroll
        for (int off = 2; off >= 1; off >>= 1) {
            lp[0] += __shfl_xor_sync(0xffffffffu, lp[0], off);
            lp[1] += __shfl_xor_sync(0xffffffffu, lp[1], off);
        }
        #pragma unroll
        for (int r = 0; r < 2; r++) {
            l_run[r] = l_run[r] * corr[r] + lp[r];
            m_run[r] = m_new[r];
        }
        #pragma unroll
        for (int nf = 0; nf < 16; nf++) {
            oacc[nf][0] *= corr[0]; oacc[nf][1] *= corr[0];
            oacc[nf][2] *= corr[1]; oacc[nf][3] *= corr[1];
        }

        // Tile fully below/at diagonal for every row of this CTA -> P == 0
        const bool pv_skip = msk && (kbase + BKT - 1 <= qbase);
        if (!pv_skip) {
            // masked P -> smem (tf32-rounded)
            const int rowg0 = qbase + r0w + lr;
            const int rowg1 = rowg0 + 8;
            #pragma unroll
            for (int nf = 0; nf < 4; nf++) {
                const int col = nf * 8 + 2 * lc;
                const int kidx = kbase + col;
                const bool z00 = msk && (kidx     <= rowg0);
                const bool z01 = msk && (kidx + 1 <= rowg0);
                const bool z10 = msk && (kidx     <= rowg1);
                const bool z11 = msk && (kidx + 1 <= rowg1);
                Ps[(r0w + lr) * PP + col]         = z00 ? 0.0f : to_tf32(sacc[nf][0]);
                Ps[(r0w + lr) * PP + col + 1]     = z01 ? 0.0f : to_tf32(sacc[nf][1]);
                Ps[(r0w + lr + 8) * PP + col]     = z10 ? 0.0f : to_tf32(sacc[nf][2]);
                Ps[(r0w + lr + 8) * PP + col + 1] = z11 ? 0.0f : to_tf32(sacc[nf][3]);
            }
            __syncwarp();

            // ---- O += P @ V ----
            #pragma unroll 2
            for (int jf = 0; jf < 4; jf++) {
                const int j = jf * 8;
                float a[4];
                a[0] = Ps[(r0w + lr) * PP + j + lc];
                a[1] = Ps[(r0w + lr + 8) * PP + j + lc];
                a[2] = Ps[(r0w + lr) * PP + j + lc + 4];
                a[3] = Ps[(r0w + lr + 8) * PP + j + lc + 4];
                #pragma unroll
                for (int nf = 0; nf < 16; nf++) {
                    float bfr[2];
                    bfr[0] = Vb[(j + lc) * VP + nf * 8 + lr];
                    bfr[1] = Vb[(j + lc + 4) * VP + nf * 8 + lr];
                    mma_tf32(oacc[nf], a, bfr);
                }
            }
            __syncwarp();
        }
    }

    // Epilogue: unnormalized partial O + (m, l) for the combine pass
    float* Pog = g_po + ((size_t)(split * B_ + b) * LQ_ + qbase) * PD_;
    #pragma unroll
    for (int nf = 0; nf < 16; nf++) {
        const int row = r0w + lr;
        const int col = nf * 8 + 2 * lc;
        *(float2*)(Pog + (size_t)row * PD_ + col) =
            make_float2(oacc[nf][0], oacc[nf][1]);
        *(float2*)(Pog + (size_t)(row + 8) * PD_ + col) =
            make_float2(oacc[nf][2], oacc[nf][3]);
    }
    if (lc == 0) {
        float* mlg = g_ml + ((size_t)(split * B_ + b) * LQ_ + qbase) * 2;
        *(float2*)(mlg + (size_t)(r0w + lr) * 2)     = make_float2(m_run[0], l_run[0]);
        *(float2*)(mlg + (size_t)(r0w + lr + 8) * 2) = make_float2(m_run[1], l_run[1]);
    }
}

// ---------------------------------------------------------------------------
// Split-KV combine: out = (O0*e^{m0-m} + O1*e^{m1-m}) / (l0*e^{m0-m} + l1*e^{m1-m})
// (proven in R4)
// ---------------------------------------------------------------------------
__global__ __launch_bounds__(256) void combine_kernel(float* __restrict__ out)
{
    const int idx = blockIdx.x * 256 + threadIdx.x;   // one float4 of out
    const int row = idx >> 5;                          // PD/4 = 32 float4 per row
    const int c4 = (idx & 31) * 4;

    const float2 ml0 = *(const float2*)(g_ml + (size_t)row * 2);
    const float2 ml1 = *(const float2*)(g_ml + ((size_t)B_ * LQ_ + row) * 2);
    const float m = fmaxf(ml0.x, ml1.x);
    const float w0 = __expf(ml0.x - m);
    const float w1 = __expf(ml1.x - m);
    const float inv = 1.0f / (ml0.y * w0 + ml1.y * w1);

    const float4 p0 = *(const float4*)(g_po + (size_t)row * PD_ + c4);
    const float4 p1 = *(const float4*)(g_po + ((size_t)B_ * LQ_ + row) * (size_t)PD_ + c4);
    float4 o;
    o.x = (p0.x * w0 + p1.x * w1) * inv;
    o.y = (p0.y * w0 + p1.y * w1) * inv;
    o.z = (p0.z * w0 + p1.z * w1) * inv;
    o.w = (p0.w * w0 + p1.w * w1) * inv;
    *(float4*)(out + (size_t)row * PD_ + c4) = o;
}

// ---------------------------------------------------------------------------
extern "C" void kernel_launch(void* const* d_in, const int* in_sizes, int n_in,
                              void* d_out, int out_size)
{
    const float* x  = (const float*)d_in[0];
    const float* y  = (const float*)d_in[1];
    const float* Wq = (const float*)d_in[2];
    const float* bq = (const float*)d_in[3];
    const float* Wk = (const float*)d_in[4];
    const float* bk = (const float*)d_in[5];
    const float* Wv = (const float*)d_in[6];
    const float* bv = (const float*)d_in[7];
    const int* maskp = (const int*)d_in[8];
    float* out = (float*)d_out;

    (void)in_sizes; (void)n_in; (void)out_size;

    cudaFuncSetAttribute(attn_kernel,
                         cudaFuncAttributeMaxDynamicSharedMemorySize, SMEM_BYTES);

    dim3 pg(128, 3);
    proj_kernel<<<pg, 256>>>(x, y, Wq, bq, Wk, bk, Wv, bv);

    dim3 ag(LQ_ / BQ, B_, NSPLIT);
    attn_kernel<<<ag, 128, SMEM_BYTES>>>(maskp);

    combine_kernel<<<(B_ * LQ_ * PD_ / 4) / 256, 256>>>(out);
}

// round 10
// speedup vs baseline: 1.2133x; 1.0585x over previous
#include <cuda_runtime.h>
#include <cuda_pipeline.h>
#include <math.h>

#define B_   4
#define LQ_  2048
#define LK_  2048
#define XS_  1024
#define PD_  128
#define NSPLIT 2

// Scratch (device globals: no allocation allowed). g_q/k/v hold TF32-rounded
// projections; g_po/g_ml hold split-KV partial outputs.
__device__ float g_q[B_ * LQ_ * PD_];
__device__ float g_k[B_ * LK_ * PD_];
__device__ float g_v[B_ * LK_ * PD_];
__device__ float g_po[NSPLIT * B_ * LQ_ * PD_];
__device__ float g_ml[NSPLIT * B_ * LQ_ * 2];

__device__ __forceinline__ float to_tf32(float x) {
    float r;
    asm("cvt.rna.tf32.f32 %0, %1;" : "=f"(r) : "f"(x));
    return r;
}

// D += A*B, m16n8k8 tf32. a: 4 regs, b: 2 regs, c: 4 fp32.
__device__ __forceinline__ void mma_tf32(float* c, const float* a, const float* b) {
    asm volatile(
        "mma.sync.aligned.m16n8k8.row.col.f32.tf32.tf32.f32 "
        "{%0,%1,%2,%3}, {%4,%5,%6,%7}, {%8,%9}, {%0,%1,%2,%3};\n"
        : "+f"(c[0]), "+f"(c[1]), "+f"(c[2]), "+f"(c[3])
        : "r"(__float_as_uint(a[0])), "r"(__float_as_uint(a[1])),
          "r"(__float_as_uint(a[2])), "r"(__float_as_uint(a[3])),
          "r"(__float_as_uint(b[0])), "r"(__float_as_uint(b[1])));
}

// ---------------------------------------------------------------------------
// Projection GEMM (tf32): C[8192,128] = A[8192,1024]@W[1024,128]+b
// CTA tile 64x128, grid (128,3)=384 CTAs (wave-balanced). 128 thr = 4 warps
// (2m x 2n), warp tile 32x64 -> B-fragments reused by 2 m-frags:
// LDS words/MMA drops 2.5 -> 1.5 vs the R6/R8 16x64 warp tile.
// BK=32, register-staged prefetch; As[m][k] pitch 36, Ws[k][n] pitch 136
// (both patterns proven conflict-free since R3).
// ---------------------------------------------------------------------------
#define PA_PITCH 36
#define PW_PITCH 136

__global__ __launch_bounds__(128) void proj_kernel(
    const float* __restrict__ x, const float* __restrict__ y,
    const float* __restrict__ Wq, const float* __restrict__ bq,
    const float* __restrict__ Wk, const float* __restrict__ bk,
    const float* __restrict__ Wv, const float* __restrict__ bv)
{
    const float* A; const float* W; const float* bias; float* C;
    if (blockIdx.y == 0)      { A = x; W = Wq; bias = bq; C = g_q; }
    else if (blockIdx.y == 1) { A = y; W = Wk; bias = bk; C = g_k; }
    else                      { A = y; W = Wv; bias = bv; C = g_v; }

    __shared__ float As[64 * PA_PITCH];    // [m][k], BK=32 cols used
    __shared__ float Ws[32 * PW_PITCH];    // [k][n]

    const int tid  = threadIdx.x;
    const int wid  = tid >> 5;
    const int lane = tid & 31;
    const int lr = lane >> 2, lc = lane & 3;
    const int rw = (wid & 1) * 32;   // warp row base within tile
    const int cw = (wid >> 1) * 64;  // warp col base within tile
    const int row0 = blockIdx.x * 64;

    // A: 64 rows x 8 float4 along k (4/thread); W: 32 k-rows x 32 float4 (8/thread)
    float4 rA[4], rW[8];
    #pragma unroll
    for (int i = 0; i < 4; i++) {
        const int g = tid + i * 128;
        rA[i] = *(const float4*)(A + (size_t)(row0 + (g >> 3)) * XS_ + (g & 7) * 4);
    }
    #pragma unroll
    for (int i = 0; i < 8; i++) {
        const int g = tid + i * 128;
        rW[i] = *(const float4*)(W + (size_t)(g >> 5) * PD_ + (g & 31) * 4);
    }

    float acc[2][8][4];
    #pragma unroll
    for (int mf = 0; mf < 2; mf++)
        #pragma unroll
        for (int nf = 0; nf < 8; nf++)
            #pragma unroll
            for (int r = 0; r < 4; r++) acc[mf][nf][r] = 0.0f;

    for (int c = 0; c < 32; c++) {
        __syncthreads();
        #pragma unroll
        for (int i = 0; i < 4; i++) {
            const int g = tid + i * 128;
            const int ar = g >> 3, ak = (g & 7) * 4;
            As[ar * PA_PITCH + ak + 0] = to_tf32(rA[i].x);
            As[ar * PA_PITCH + ak + 1] = to_tf32(rA[i].y);
            As[ar * PA_PITCH + ak + 2] = to_tf32(rA[i].z);
            As[ar * PA_PITCH + ak + 3] = to_tf32(rA[i].w);
        }
        #pragma unroll
        for (int i = 0; i < 8; i++) {
            const int g = tid + i * 128;
            const int wk = g >> 5, wn = (g & 31) * 4;
            Ws[wk * PW_PITCH + wn + 0] = to_tf32(rW[i].x);
            Ws[wk * PW_PITCH + wn + 1] = to_tf32(rW[i].y);
            Ws[wk * PW_PITCH + wn + 2] = to_tf32(rW[i].z);
            Ws[wk * PW_PITCH + wn + 3] = to_tf32(rW[i].w);
        }
        __syncthreads();

        if (c < 31) {
            const int k0 = (c + 1) * 32;
            #pragma unroll
            for (int i = 0; i < 4; i++) {
                const int g = tid + i * 128;
                rA[i] = *(const float4*)(A + (size_t)(row0 + (g >> 3)) * XS_ + k0 + (g & 7) * 4);
            }
            #pragma unroll
            for (int i = 0; i < 8; i++) {
                const int g = tid + i * 128;
                rW[i] = *(const float4*)(W + (size_t)(k0 + (g >> 5)) * PD_ + (g & 31) * 4);
            }
        }

        #pragma unroll
        for (int kf = 0; kf < 4; kf++) {
            const int k = kf * 8;
            float a[2][4];
            #pragma unroll
            for (int mf = 0; mf < 2; mf++) {
                const int r = rw + mf * 16 + lr;
                a[mf][0] = As[r * PA_PITCH + k + lc];
                a[mf][1] = As[(r + 8) * PA_PITCH + k + lc];
                a[mf][2] = As[r * PA_PITCH + k + lc + 4];
                a[mf][3] = As[(r + 8) * PA_PITCH + k + lc + 4];
            }
            #pragma unroll
            for (int nf = 0; nf < 8; nf++) {
                float b[2];
                const int col = cw + nf * 8 + lr;
                b[0] = Ws[(k + lc) * PW_PITCH + col];
                b[1] = Ws[(k + lc + 4) * PW_PITCH + col];
                mma_tf32(acc[0][nf], a[0], b);
                mma_tf32(acc[1][nf], a[1], b);
            }
        }
    }

    // Epilogue: +bias, round to tf32, store
    #pragma unroll
    for (int mf = 0; mf < 2; mf++) {
        #pragma unroll
        for (int nf = 0; nf < 8; nf++) {
            const int row = row0 + rw + mf * 16 + lr;
            const int col = cw + nf * 8 + 2 * lc;
            const float2 bb = *(const float2*)(bias + col);
            float2 o0, o1;
            o0.x = to_tf32(acc[mf][nf][0] + bb.x);
            o0.y = to_tf32(acc[mf][nf][1] + bb.y);
            o1.x = to_tf32(acc[mf][nf][2] + bb.x);
            o1.y = to_tf32(acc[mf][nf][3] + bb.y);
            *(float2*)(C + (size_t)row * PD_ + col) = o0;
            *(float2*)(C + (size_t)(row + 8) * PD_ + col) = o1;
        }
    }
}

// ---------------------------------------------------------------------------
// Flash attention (R8 version, verbatim): tf32 mma.sync, split-KV x2, BKT=32,
// 2 CTAs/SM. Post-softmax triu(k=1) mask.
// ---------------------------------------------------------------------------
#define BQ  64
#define BKT 32
#define NT  (LK_ / BKT / NSPLIT)   // 32 tiles per split
#define QP  132
#define VP  136
#define PP  36
#define SMF_Q  0
#define SMF_K  (64 * QP)
#define SMF_V  (SMF_K + 2 * BKT * QP)
#define SMF_P  (SMF_V + 2 * BKT * VP)
#define SMEM_FLOATS (SMF_P + 64 * PP)
#define SMEM_BYTES  (SMEM_FLOATS * 4)   // 111,616 B

__global__ __launch_bounds__(128) void attn_kernel(const int* __restrict__ maskp)
{
    extern __shared__ float sm[];
    float* Qs = sm + SMF_Q;
    float* Ks = sm + SMF_K;
    float* Vs = sm + SMF_V;
    float* Ps = sm + SMF_P;

    const int b = blockIdx.y;
    const int qbase = blockIdx.x * BQ;
    const int split = blockIdx.z;
    const int kstart = split * (LK_ / NSPLIT);

    const float* Qg = g_q + ((size_t)b * LQ_ + qbase) * PD_;
    const float* Kg = g_k + (size_t)b * LK_ * PD_;
    const float* Vg = g_v + (size_t)b * LK_ * PD_;

    const int tid  = threadIdx.x;
    const int wid  = tid >> 5;
    const int lane = tid & 31;
    const int lr = lane >> 2, lc = lane & 3;
    const int r0w = wid * 16;
    const int msk = *maskp;
    const float SCALE = 0.0883883476483184f;

    #pragma unroll
    for (int i = 0; i < 16; i++) {
        const int g = tid + i * 128;
        const int j = g >> 5, d4 = (g & 31) * 4;
        __pipeline_memcpy_async(&Qs[j * QP + d4], Qg + (size_t)j * PD_ + d4, 16);
    }
    #pragma unroll
    for (int i = 0; i < 8; i++) {
        const int g = tid + i * 128;
        const int j = g >> 5, d4 = (g & 31) * 4;
        __pipeline_memcpy_async(&Ks[j * QP + d4],
                                Kg + (size_t)(kstart + j) * PD_ + d4, 16);
        __pipeline_memcpy_async(&Vs[j * VP + d4],
                                Vg + (size_t)(kstart + j) * PD_ + d4, 16);
    }
    __pipeline_commit();

    float oacc[16][4];
    #pragma unroll
    for (int nf = 0; nf < 16; nf++)
        #pragma unroll
        for (int r = 0; r < 4; r++) oacc[nf][r] = 0.0f;
    float m_run[2] = {-1e30f, -1e30f};
    float l_run[2] = {0.0f, 0.0f};

    for (int t = 0; t < NT; t++) {
        const int kbase = kstart + t * BKT;
        const int buf = t & 1;
        float* Kb = Ks + buf * BKT * QP;
        float* Vb = Vs + buf * BKT * VP;

        __pipeline_wait_prior(0);
        __syncthreads();

        if (t + 1 < NT) {
            const int nb = (t + 1) & 1;
            float* Kn = Ks + nb * BKT * QP;
            float* Vn = Vs + nb * BKT * VP;
            const float* Kgs = Kg + (size_t)(kbase + BKT) * PD_;
            const float* Vgs = Vg + (size_t)(kbase + BKT) * PD_;
            #pragma unroll
            for (int i = 0; i < 8; i++) {
                const int g = tid + i * 128;
                const int j = g >> 5, d4 = (g & 31) * 4;
                __pipeline_memcpy_async(&Kn[j * QP + d4], Kgs + (size_t)j * PD_ + d4, 16);
                __pipeline_memcpy_async(&Vn[j * VP + d4], Vgs + (size_t)j * PD_ + d4, 16);
            }
            __pipeline_commit();
        }

        float sacc[4][4];
        #pragma unroll
        for (int nf = 0; nf < 4; nf++)
            #pragma unroll
            for (int r = 0; r < 4; r++) sacc[nf][r] = 0.0f;

        #pragma unroll 4
        for (int kf = 0; kf < 16; kf++) {
            const int k = kf * 8;
            float a[4];
            a[0] = Qs[(r0w + lr) * QP + k + lc];
            a[1] = Qs[(r0w + lr + 8) * QP + k + lc];
            a[2] = Qs[(r0w + lr) * QP + k + lc + 4];
            a[3] = Qs[(r0w + lr + 8) * QP + k + lc + 4];
            #pragma unroll
            for (int nf = 0; nf < 4; nf++) {
                float bfr[2];
                bfr[0] = Kb[(nf * 8 + lr) * QP + k + lc];
                bfr[1] = Kb[(nf * 8 + lr) * QP + k + lc + 4];
                mma_tf32(sacc[nf], a, bfr);
            }
        }

        #pragma unroll
        for (int nf = 0; nf < 4; nf++)
            #pragma unroll
            for (int r = 0; r < 4; r++) sacc[nf][r] *= SCALE;

        float m_t[2] = {-1e30f, -1e30f};
        #pragma unroll
        for (int nf = 0; nf < 4; nf++) {
            m_t[0] = fmaxf(m_t[0], fmaxf(sacc[nf][0], sacc[nf][1]));
            m_t[1] = fmaxf(m_t[1], fmaxf(sacc[nf][2], sacc[nf][3]));
        }
        #pragma unroll
        for (int off = 2; off >= 1; off >>= 1) {
            m_t[0] = fmaxf(m_t[0], __shfl_xor_sync(0xffffffffu, m_t[0], off));
            m_t[1] = fmaxf(m_t[1], __shfl_xor_sync(0xffffffffu, m_t[1], off));
        }
        float m_new[2], corr[2], lp[2] = {0.0f, 0.0f};
        #pragma unroll
        for (int r = 0; r < 2; r++) {
            m_new[r] = fmaxf(m_run[r], m_t[r]);
            corr[r] = __expf(m_run[r] - m_new[r]);
        }
        #pragma unroll
        for (int nf = 0; nf < 4; nf++) {
            #pragma unroll
            for (int r = 0; r < 4; r++) {
                const float e = __expf(sacc[nf][r] - m_new[r >> 1]);
                sacc[nf][r] = e;
                lp[r >> 1] += e;
            }
        }
        #pragma unroll
        for (int off = 2; off >= 1; off >>= 1) {
            lp[0] += __shfl_xor_sync(0xffffffffu, lp[0], off);
            lp[1] += __shfl_xor_sync(0xffffffffu, lp[1], off);
        }
        #pragma unroll
        for (int r = 0; r < 2; r++) {
            l_run[r] = l_run[r] * corr[r] + lp[r];
            m_run[r] = m_new[r];
        }
        #pragma unroll
        for (int nf = 0; nf < 16; nf++) {
            oacc[nf][0] *= corr[0]; oacc[nf][1] *= corr[0];
            oacc[nf][2] *= corr[1]; oacc[nf][3] *= corr[1];
        }

        const bool pv_skip = msk && (kbase + BKT - 1 <= qbase);
        if (!pv_skip) {
            const int rowg0 = qbase + r0w + lr;
            const int rowg1 = rowg0 + 8;
            #pragma unroll
            for (int nf = 0; nf < 4; nf++) {
                const int col = nf * 8 + 2 * lc;
                const int kidx = kbase + col;
                const bool z00 = msk && (kidx     <= rowg0);
                const bool z01 = msk && (kidx + 1 <= rowg0);
                const bool z10 = msk && (kidx     <= rowg1);
                const bool z11 = msk && (kidx + 1 <= rowg1);
                Ps[(r0w + lr) * PP + col]         = z00 ? 0.0f : to_tf32(sacc[nf][0]);
                Ps[(r0w + lr) * PP + col + 1]     = z01 ? 0.0f : to_tf32(sacc[nf][1]);
                Ps[(r0w + lr + 8) * PP + col]     = z10 ? 0.0f : to_tf32(sacc[nf][2]);
                Ps[(r0w + lr + 8) * PP + col + 1] = z11 ? 0.0f : to_tf32(sacc[nf][3]);
            }
            __syncwarp();

            #pragma unroll 2
            for (int jf = 0; jf < 4; jf++) {
                const int j = jf * 8;
                float a[4];
                a[0] = Ps[(r0w + lr) * PP + j + lc];
                a[1] = Ps[(r0w + lr + 8) * PP + j + lc];
                a[2] = Ps[(r0w + lr) * PP + j + lc + 4];
                a[3] = Ps[(r0w + lr + 8) * PP + j + lc + 4];
                #pragma unroll
                for (int nf = 0; nf < 16; nf++) {
                    float bfr[2];
                    bfr[0] = Vb[(j + lc) * VP + nf * 8 + lr];
                    bfr[1] = Vb[(j + lc + 4) * VP + nf * 8 + lr];
                    mma_tf32(oacc[nf], a, bfr);
                }
            }
            __syncwarp();
        }
    }

    float* Pog = g_po + ((size_t)(split * B_ + b) * LQ_ + qbase) * PD_;
    #pragma unroll
    for (int nf = 0; nf < 16; nf++) {
        const int row = r0w + lr;
        const int col = nf * 8 + 2 * lc;
        *(float2*)(Pog + (size_t)row * PD_ + col) =
            make_float2(oacc[nf][0], oacc[nf][1]);
        *(float2*)(Pog + (size_t)(row + 8) * PD_ + col) =
            make_float2(oacc[nf][2], oacc[nf][3]);
    }
    if (lc == 0) {
        float* mlg = g_ml + ((size_t)(split * B_ + b) * LQ_ + qbase) * 2;
        *(float2*)(mlg + (size_t)(r0w + lr) * 2)     = make_float2(m_run[0], l_run[0]);
        *(float2*)(mlg + (size_t)(r0w + lr + 8) * 2) = make_float2(m_run[1], l_run[1]);
    }
}

// ---------------------------------------------------------------------------
// Split-KV combine (proven in R4/R8)
// ---------------------------------------------------------------------------
__global__ __launch_bounds__(256) void combine_kernel(float* __restrict__ out)
{
    const int idx = blockIdx.x * 256 + threadIdx.x;
    const int row = idx >> 5;
    const int c4 = (idx & 31) * 4;

    const float2 ml0 = *(const float2*)(g_ml + (size_t)row * 2);
    const float2 ml1 = *(const float2*)(g_ml + ((size_t)B_ * LQ_ + row) * 2);
    const float m = fmaxf(ml0.x, ml1.x);
    const float w0 = __expf(ml0.x - m);
    const float w1 = __expf(ml1.x - m);
    const float inv = 1.0f / (ml0.y * w0 + ml1.y * w1);

    const float4 p0 = *(const float4*)(g_po + (size_t)row * PD_ + c4);
    const float4 p1 = *(const float4*)(g_po + ((size_t)B_ * LQ_ + row) * (size_t)PD_ + c4);
    float4 o;
    o.x = (p0.x * w0 + p1.x * w1) * inv;
    o.y = (p0.y * w0 + p1.y * w1) * inv;
    o.z = (p0.z * w0 + p1.z * w1) * inv;
    o.w = (p0.w * w0 + p1.w * w1) * inv;
    *(float4*)(out + (size_t)row * PD_ + c4) = o;
}

// ---------------------------------------------------------------------------
extern "C" void kernel_launch(void* const* d_in, const int* in_sizes, int n_in,
                              void* d_out, int out_size)
{
    const float* x  = (const float*)d_in[0];
    const float* y  = (const float*)d_in[1];
    const float* Wq = (const float*)d_in[2];
    const float* bq = (const float*)d_in[3];
    const float* Wk = (const float*)d_in[4];
    const float* bk = (const float*)d_in[5];
    const float* Wv = (const float*)d_in[6];
    const float* bv = (const float*)d_in[7];
    const int* maskp = (const int*)d_in[8];
    float* out = (float*)d_out;

    (void)in_sizes; (void)n_in; (void)out_size;

    cudaFuncSetAttribute(attn_kernel,
                         cudaFuncAttributeMaxDynamicSharedMemorySize, SMEM_BYTES);

    dim3 pg(128, 3);
    proj_kernel<<<pg, 128>>>(x, y, Wq, bq, Wk, bk, Wv, bv);

    dim3 ag(LQ_ / BQ, B_, NSPLIT);
    attn_kernel<<<ag, 128, SMEM_BYTES>>>(maskp);

    combine_kernel<<<(B_ * LQ_ * PD_ / 4) / 256, 256>>>(out);
}

// round 12
// speedup vs baseline: 1.6117x; 1.3283x over previous
#include <cuda_runtime.h>
#include <cuda_pipeline.h>
#include <cuda_fp16.h>
#include <math.h>
#include <stdint.h>

#define B_   4
#define LQ_  2048
#define LK_  2048
#define XS_  1024
#define PD_  128
#define NSPLIT 4

// Device-global scratch (no allocation allowed).
__device__ __half g_xh[B_ * LQ_ * XS_];     // half(x)
__device__ __half g_yh[B_ * LK_ * XS_];     // half(y)
__device__ __half g_wth[3 * PD_ * XS_];     // [mat][n][k] = half(W^T)
__device__ __half g_qh[B_ * LQ_ * PD_];     // projected q (half)
__device__ __half g_kh[B_ * LK_ * PD_];     // projected k (half)
__device__ __half g_vt[B_ * PD_ * LK_];     // projected v, TRANSPOSED [b][d][j]
__device__ float  g_po[NSPLIT * B_ * LQ_ * PD_];
__device__ float  g_ml[NSPLIT * B_ * LQ_ * 2];

// D += A*B, m16n8k16 f16 inputs, f32 accum. a: 4 words (8 halves), b: 2 words.
__device__ __forceinline__ void mma_f16(float* c, const uint32_t* a, const uint32_t* b) {
    asm volatile(
        "mma.sync.aligned.m16n8k16.row.col.f32.f16.f16.f32 "
        "{%0,%1,%2,%3}, {%4,%5,%6,%7}, {%8,%9}, {%0,%1,%2,%3};\n"
        : "+f"(c[0]), "+f"(c[1]), "+f"(c[2]), "+f"(c[3])
        : "r"(a[0]), "r"(a[1]), "r"(a[2]), "r"(a[3]), "r"(b[0]), "r"(b[1]));
}

__device__ __forceinline__ uint32_t h2u(__half2 h) {
    return *reinterpret_cast<uint32_t*>(&h);
}

// ---------------------------------------------------------------------------
// cvt_kernel: one-time fp32 -> fp16 conversion of x, y, and W (transposed).
// Threads cover x float4s, then y float4s, then W^T half4 groups.
// ---------------------------------------------------------------------------
#define NX4 (B_ * LQ_ * XS_ / 4)    // 2,097,152

__global__ __launch_bounds__(256) void cvt_kernel(
    const float* __restrict__ x, const float* __restrict__ y,
    const float* __restrict__ Wq, const float* __restrict__ Wk,
    const float* __restrict__ Wv)
{
    const int idx = blockIdx.x * 256 + threadIdx.x;
    if (idx < NX4) {
        const float4 f = *(const float4*)(x + (size_t)idx * 4);
        __half2* dst = (__half2*)(g_xh + (size_t)idx * 4);
        dst[0] = __floats2half2_rn(f.x, f.y);
        dst[1] = __floats2half2_rn(f.z, f.w);
    } else if (idx < 2 * NX4) {
        const int i = idx - NX4;
        const float4 f = *(const float4*)(y + (size_t)i * 4);
        __half2* dst = (__half2*)(g_yh + (size_t)i * 4);
        dst[0] = __floats2half2_rn(f.x, f.y);
        dst[1] = __floats2half2_rn(f.z, f.w);
    } else {
        const int i = idx - 2 * NX4;          // 0 .. 98303
        if (i < 3 * PD_ * XS_ / 4) {
            const int mat = i / (PD_ * XS_ / 4);
            const int r = i % (PD_ * XS_ / 4);
            const int n = r >> 8;              // 0..127
            const int k4 = (r & 255) * 4;      // 0..1020
            const float* W = (mat == 0) ? Wq : ((mat == 1) ? Wk : Wv);
            const float f0 = W[(size_t)(k4 + 0) * PD_ + n];
            const float f1 = W[(size_t)(k4 + 1) * PD_ + n];
            const float f2 = W[(size_t)(k4 + 2) * PD_ + n];
            const float f3 = W[(size_t)(k4 + 3) * PD_ + n];
            __half2* dst = (__half2*)(g_wth + ((size_t)mat * PD_ + n) * XS_ + k4);
            dst[0] = __floats2half2_rn(f0, f1);
            dst[1] = __floats2half2_rn(f2, f3);
        }
    }
}

// ---------------------------------------------------------------------------
// Projection GEMM (fp16 m16n8k16): C[8192,128] = A[8192,1024]@W[1024,128]+b
// CTA tile 64x128, grid (128,3). 128 thr = 4 warps (2m x 2n), warp 32x64.
// A (half [m][k]) and W^T (half [n][k]) both cp.async'd raw; BK=32, double buf.
// smem pitches 20 words (16 used + 4 pad): frag-load banks (20*lr + lc) mod 32
// all distinct.  Epilogue: +bias fp32, round to half; V written transposed.
// ---------------------------------------------------------------------------
#define PAW 20
#define PBW 20

__global__ __launch_bounds__(128) void proj_kernel(
    const float* __restrict__ bq, const float* __restrict__ bk,
    const float* __restrict__ bv)
{
    __shared__ uint32_t As[2 * 64 * PAW];    // [buf][m][k-words]
    __shared__ uint32_t Bs[2 * 128 * PBW];   // [buf][n][k-words]

    const int mat = blockIdx.y;
    const __half* A = (mat == 0) ? g_xh : g_yh;
    const float* bias = (mat == 0) ? bq : ((mat == 1) ? bk : bv);
    const __half* Bw = g_wth + (size_t)mat * PD_ * XS_;
    const int row0 = blockIdx.x * 64;

    const int tid  = threadIdx.x;
    const int wid  = tid >> 5;
    const int lane = tid & 31;
    const int lr = lane >> 2, lc = lane & 3;
    const int rw = (wid & 1) * 32;
    const int cw = (wid >> 1) * 64;

    // prologue: chunk 0
    #pragma unroll
    for (int i = 0; i < 2; i++) {
        const int g = tid + i * 128;
        const int m = g >> 2, cq = g & 3;
        __pipeline_memcpy_async(&As[m * PAW + cq * 4],
                                A + (size_t)(row0 + m) * XS_ + cq * 8, 16);
    }
    #pragma unroll
    for (int i = 0; i < 4; i++) {
        const int g = tid + i * 128;
        const int n = g >> 2, cq = g & 3;
        __pipeline_memcpy_async(&Bs[n * PBW + cq * 4],
                                Bw + (size_t)n * XS_ + cq * 8, 16);
    }
    __pipeline_commit();

    float acc[2][8][4];
    #pragma unroll
    for (int mf = 0; mf < 2; mf++)
        #pragma unroll
        for (int nf = 0; nf < 8; nf++)
            #pragma unroll
            for (int r = 0; r < 4; r++) acc[mf][nf][r] = 0.0f;

    for (int c = 0; c < 32; c++) {
        const int buf = c & 1;
        __pipeline_wait_prior(0);
        __syncthreads();

        if (c < 31) {
            const int nb = (c + 1) & 1;
            const int kc = (c + 1) * 32;
            #pragma unroll
            for (int i = 0; i < 2; i++) {
                const int g = tid + i * 128;
                const int m = g >> 2, cq = g & 3;
                __pipeline_memcpy_async(&As[nb * 64 * PAW + m * PAW + cq * 4],
                                        A + (size_t)(row0 + m) * XS_ + kc + cq * 8, 16);
            }
            #pragma unroll
            for (int i = 0; i < 4; i++) {
                const int g = tid + i * 128;
                const int n = g >> 2, cq = g & 3;
                __pipeline_memcpy_async(&Bs[nb * 128 * PBW + n * PBW + cq * 4],
                                        Bw + (size_t)n * XS_ + kc + cq * 8, 16);
            }
            __pipeline_commit();
        }

        const uint32_t* Ab = As + buf * 64 * PAW;
        const uint32_t* Bb = Bs + buf * 128 * PBW;
        #pragma unroll
        for (int kf = 0; kf < 2; kf++) {
            const int kw = kf * 8;
            uint32_t a[2][4];
            #pragma unroll
            for (int mf = 0; mf < 2; mf++) {
                const int r = rw + mf * 16 + lr;
                a[mf][0] = Ab[r * PAW + kw + lc];
                a[mf][1] = Ab[(r + 8) * PAW + kw + lc];
                a[mf][2] = Ab[r * PAW + kw + lc + 4];
                a[mf][3] = Ab[(r + 8) * PAW + kw + lc + 4];
            }
            #pragma unroll
            for (int nf = 0; nf < 8; nf++) {
                uint32_t b[2];
                const int col = cw + nf * 8 + lr;
                b[0] = Bb[col * PBW + kw + lc];
                b[1] = Bb[col * PBW + kw + lc + 4];
                mma_f16(acc[0][nf], a[0], b);
                mma_f16(acc[1][nf], a[1], b);
            }
        }
    }

    // Epilogue: +bias, round to half.  Q/K natural layout; V transposed [b][d][j].
    #pragma unroll
    for (int mf = 0; mf < 2; mf++) {
        #pragma unroll
        for (int nf = 0; nf < 8; nf++) {
            const int row = row0 + rw + mf * 16 + lr;
            const int col = cw + nf * 8 + 2 * lc;
            const float2 bb = *(const float2*)(bias + col);
            const float v00 = acc[mf][nf][0] + bb.x;
            const float v01 = acc[mf][nf][1] + bb.y;
            const float v10 = acc[mf][nf][2] + bb.x;
            const float v11 = acc[mf][nf][3] + bb.y;
            if (mat < 2) {
                __half* C = (mat == 0) ? g_qh : g_kh;
                *(__half2*)(C + (size_t)row * PD_ + col) = __floats2half2_rn(v00, v01);
                *(__half2*)(C + (size_t)(row + 8) * PD_ + col) = __floats2half2_rn(v10, v11);
            } else {
                const int bi = row >> 11, j = row & 2047;   // row+8 stays same b
                g_vt[((size_t)bi * PD_ + col) * LK_ + j]         = __float2half_rn(v00);
                g_vt[((size_t)bi * PD_ + col + 1) * LK_ + j]     = __float2half_rn(v01);
                g_vt[((size_t)bi * PD_ + col) * LK_ + j + 8]     = __float2half_rn(v10);
                g_vt[((size_t)bi * PD_ + col + 1) * LK_ + j + 8] = __float2half_rn(v11);
            }
        }
    }
}

// ---------------------------------------------------------------------------
// Flash attention (fp16 m16n8k16), split-KV x4, post-softmax triu(k=1) mask.
// grid (32, 4, 4), 128 thr = 4 warps x 16 rows (proven R8 structure).
// smem 60,416 B -> 3 CTAs/SM.  Q/K cp.async natural [seq][d]; V cp.async from
// pre-transposed g_vt [d][j]; P packed half2.  All frag banks distinct.
// ---------------------------------------------------------------------------
#define BQ  64
#define BKT 32
#define NT  (LK_ / BKT / NSPLIT)   // 16 tiles per split
#define QWP 68
#define KWP 68
#define VWP 20
#define PWP 20
#define SQ_ 0
#define SK_ (64 * QWP)                 // 4352
#define SV_ (SK_ + 2 * 32 * KWP)       // 8704
#define SP_ (SV_ + 2 * 128 * VWP)      // 13824
#define SMEM_WORDS (SP_ + 64 * PWP)    // 15104
#define SMEM_BYTES (SMEM_WORDS * 4)    // 60416

__global__ __launch_bounds__(128, 3) void attn_kernel(const int* __restrict__ maskp)
{
    extern __shared__ uint32_t smw[];
    uint32_t* Qw = smw + SQ_;    // [r][d-words] pitch 68
    uint32_t* Kw = smw + SK_;    // buf*[j][d-words] pitch 68
    uint32_t* Vw = smw + SV_;    // buf*[d][j-words] pitch 20
    uint32_t* Pw = smw + SP_;    // [r][j-words] pitch 20

    const int b = blockIdx.y;
    const int qbase = blockIdx.x * BQ;
    const int split = blockIdx.z;
    const int kstart = split * (LK_ / NSPLIT);

    const __half* Qg = g_qh + ((size_t)b * LQ_ + qbase) * PD_;
    const __half* Kg = g_kh + (size_t)b * LK_ * PD_;
    const __half* Vg = g_vt + (size_t)b * PD_ * LK_;   // [d][j]

    const int tid  = threadIdx.x;
    const int wid  = tid >> 5;
    const int lane = tid & 31;
    const int lr = lane >> 2, lc = lane & 3;
    const int r0w = wid * 16;
    const int msk = *maskp;
    const float SCALE = 0.0883883476483184f;  // 1/sqrt(128)

    // Prologue: Q (8/thr), K tile 0 (4/thr), V tile 0 (4/thr)
    #pragma unroll
    for (int i = 0; i < 8; i++) {
        const int g = tid + i * 128;
        const int r = g >> 4, cq = g & 15;
        __pipeline_memcpy_async(&Qw[r * QWP + cq * 4],
                                Qg + (size_t)r * PD_ + cq * 8, 16);
    }
    #pragma unroll
    for (int i = 0; i < 4; i++) {
        const int g = tid + i * 128;
        const int r = g >> 4, cq = g & 15;
        __pipeline_memcpy_async(&Kw[r * KWP + cq * 4],
                                Kg + (size_t)(kstart + r) * PD_ + cq * 8, 16);
    }
    #pragma unroll
    for (int i = 0; i < 4; i++) {
        const int g = tid + i * 128;
        const int d = g >> 2, cq = g & 3;
        __pipeline_memcpy_async(&Vw[d * VWP + cq * 4],
                                Vg + (size_t)d * LK_ + kstart + cq * 8, 16);
    }
    __pipeline_commit();

    float oacc[16][4];
    #pragma unroll
    for (int nf = 0; nf < 16; nf++)
        #pragma unroll
        for (int r = 0; r < 4; r++) oacc[nf][r] = 0.0f;
    float m_run[2] = {-1e30f, -1e30f};
    float l_run[2] = {0.0f, 0.0f};

    for (int t = 0; t < NT; t++) {
        const int kbase = kstart + t * BKT;
        const int buf = t & 1;
        const uint32_t* Kb = Kw + buf * 32 * KWP;
        const uint32_t* Vb = Vw + buf * 128 * VWP;

        __pipeline_wait_prior(0);
        __syncthreads();

        if (t + 1 < NT) {
            const int nb = (t + 1) & 1;
            uint32_t* Kn = Kw + nb * 32 * KWP;
            uint32_t* Vn = Vw + nb * 128 * VWP;
            #pragma unroll
            for (int i = 0; i < 4; i++) {
                const int g = tid + i * 128;
                const int r = g >> 4, cq = g & 15;
                __pipeline_memcpy_async(&Kn[r * KWP + cq * 4],
                                        Kg + (size_t)(kbase + BKT + r) * PD_ + cq * 8, 16);
            }
            #pragma unroll
            for (int i = 0; i < 4; i++) {
                const int g = tid + i * 128;
                const int d = g >> 2, cq = g & 3;
                __pipeline_memcpy_async(&Vn[d * VWP + cq * 4],
                                        Vg + (size_t)d * LK_ + kbase + BKT + cq * 8, 16);
            }
            __pipeline_commit();
        }

        // ---- S = Q @ K^T (warp: 16 rows x 32 cols; 8 kf x 4 nf = 32 MMA) ----
        float sacc[4][4];
        #pragma unroll
        for (int nf = 0; nf < 4; nf++)
            #pragma unroll
            for (int r = 0; r < 4; r++) sacc[nf][r] = 0.0f;

        #pragma unroll 4
        for (int kf = 0; kf < 8; kf++) {
            const int kw = kf * 8;
            uint32_t a[4];
            a[0] = Qw[(r0w + lr) * QWP + kw + lc];
            a[1] = Qw[(r0w + lr + 8) * QWP + kw + lc];
            a[2] = Qw[(r0w + lr) * QWP + kw + lc + 4];
            a[3] = Qw[(r0w + lr + 8) * QWP + kw + lc + 4];
            #pragma unroll
            for (int nf = 0; nf < 4; nf++) {
                uint32_t bfr[2];
                bfr[0] = Kb[(nf * 8 + lr) * KWP + kw + lc];
                bfr[1] = Kb[(nf * 8 + lr) * KWP + kw + lc + 4];
                mma_f16(sacc[nf], a, bfr);
            }
        }

        // ---- online softmax (warp-local; rows lr, lr+8) ----
        #pragma unroll
        for (int nf = 0; nf < 4; nf++)
            #pragma unroll
            for (int r = 0; r < 4; r++) sacc[nf][r] *= SCALE;

        float m_t[2] = {-1e30f, -1e30f};
        #pragma unroll
        for (int nf = 0; nf < 4; nf++) {
            m_t[0] = fmaxf(m_t[0], fmaxf(sacc[nf][0], sacc[nf][1]));
            m_t[1] = fmaxf(m_t[1], fmaxf(sacc[nf][2], sacc[nf][3]));
        }
        #pragma unroll
        for (int off = 2; off >= 1; off >>= 1) {
            m_t[0] = fmaxf(m_t[0], __shfl_xor_sync(0xffffffffu, m_t[0], off));
            m_t[1] = fmaxf(m_t[1], __shfl_xor_sync(0xffffffffu, m_t[1], off));
        }
        float m_new[2], corr[2], lp[2] = {0.0f, 0.0f};
        #pragma unroll
        for (int r = 0; r < 2; r++) {
            m_new[r] = fmaxf(m_run[r], m_t[r]);
            corr[r] = __expf(m_run[r] - m_new[r]);
        }
        #pragma unroll
        for (int nf = 0; nf < 4; nf++) {
            #pragma unroll
            for (int r = 0; r < 4; r++) {
                const float e = __expf(sacc[nf][r] - m_new[r >> 1]);
                sacc[nf][r] = e;
                lp[r >> 1] += e;
            }
        }
        #pragma unroll
        for (int off = 2; off >= 1; off >>= 1) {
            lp[0] += __shfl_xor_sync(0xffffffffu, lp[0], off);
            lp[1] += __shfl_xor_sync(0xffffffffu, lp[1], off);
        }
        #pragma unroll
        for (int r = 0; r < 2; r++) {
            l_run[r] = l_run[r] * corr[r] + lp[r];
            m_run[r] = m_new[r];
        }
        #pragma unroll
        for (int nf = 0; nf < 16; nf++) {
            oacc[nf][0] *= corr[0]; oacc[nf][1] *= corr[0];
            oacc[nf][2] *= corr[1]; oacc[nf][3] *= corr[1];
        }

        // Tile fully below/at diagonal for all rows of this CTA -> P == 0
        const bool pv_skip = msk && (kbase + BKT - 1 <= qbase);
        if (!pv_skip) {
            // masked P -> smem as packed half2
            const int rowg0 = qbase + r0w + lr;
            const int rowg1 = rowg0 + 8;
            #pragma unroll
            for (int nf = 0; nf < 4; nf++) {
                const int col = nf * 8 + 2 * lc;
                const int kidx = kbase + col;
                const bool z00 = msk && (kidx     <= rowg0);
                const bool z01 = msk && (kidx + 1 <= rowg0);
                const bool z10 = msk && (kidx     <= rowg1);
                const bool z11 = msk && (kidx + 1 <= rowg1);
                Pw[(r0w + lr) * PWP + nf * 4 + lc] =
                    h2u(__floats2half2_rn(z00 ? 0.0f : sacc[nf][0],
                                          z01 ? 0.0f : sacc[nf][1]));
                Pw[(r0w + lr + 8) * PWP + nf * 4 + lc] =
                    h2u(__floats2half2_rn(z10 ? 0.0f : sacc[nf][2],
                                          z11 ? 0.0f : sacc[nf][3]));
            }
            __syncwarp();

            // ---- O += P @ V (2 jf x 16 nf = 32 MMA) ----
            #pragma unroll
            for (int jf = 0; jf < 2; jf++) {
                const int jw = jf * 8;
                uint32_t pa[4];
                pa[0] = Pw[(r0w + lr) * PWP + jw + lc];
                pa[1] = Pw[(r0w + lr + 8) * PWP + jw + lc];
                pa[2] = Pw[(r0w + lr) * PWP + jw + lc + 4];
                pa[3] = Pw[(r0w + lr + 8) * PWP + jw + lc + 4];
                #pragma unroll
                for (int nf = 0; nf < 16; nf++) {
                    uint32_t vb[2];
                    vb[0] = Vb[(nf * 8 + lr) * VWP + jw + lc];
                    vb[1] = Vb[(nf * 8 + lr) * VWP + jw + lc + 4];
                    mma_f16(oacc[nf], pa, vb);
                }
            }
            __syncwarp();
        }
    }

    // Epilogue: unnormalized partial O + (m, l)
    float* Pog = g_po + ((size_t)(split * B_ + b) * LQ_ + qbase) * PD_;
    #pragma unroll
    for (int nf = 0; nf < 16; nf++) {
        const int row = r0w + lr;
        const int col = nf * 8 + 2 * lc;
        *(float2*)(Pog + (size_t)row * PD_ + col) =
            make_float2(oacc[nf][0], oacc[nf][1]);
        *(float2*)(Pog + (size_t)(row + 8) * PD_ + col) =
            make_float2(oacc[nf][2], oacc[nf][3]);
    }
    if (lc == 0) {
        float* mlg = g_ml + ((size_t)(split * B_ + b) * LQ_ + qbase) * 2;
        *(float2*)(mlg + (size_t)(r0w + lr) * 2)     = make_float2(m_run[0], l_run[0]);
        *(float2*)(mlg + (size_t)(r0w + lr + 8) * 2) = make_float2(m_run[1], l_run[1]);
    }
}

// ---------------------------------------------------------------------------
// Split-KV combine over NSPLIT=4 partials.
// ---------------------------------------------------------------------------
__global__ __launch_bounds__(256) void combine_kernel(float* __restrict__ out)
{
    const int idx = blockIdx.x * 256 + threadIdx.x;   // one float4 of out
    const int row = idx >> 5;                          // global (b*LQ + q)
    const int c4 = (idx & 31) * 4;

    float2 ml[NSPLIT];
    #pragma unroll
    for (int s = 0; s < NSPLIT; s++)
        ml[s] = *(const float2*)(g_ml + ((size_t)s * B_ * LQ_ + row) * 2);

    float m = ml[0].x;
    #pragma unroll
    for (int s = 1; s < NSPLIT; s++) m = fmaxf(m, ml[s].x);

    float w[NSPLIT], denom = 0.0f;
    #pragma unroll
    for (int s = 0; s < NSPLIT; s++) {
        w[s] = __expf(ml[s].x - m);
        denom += ml[s].y * w[s];
    }
    const float inv = 1.0f / denom;

    float4 o = make_float4(0.0f, 0.0f, 0.0f, 0.0f);
    #pragma unroll
    for (int s = 0; s < NSPLIT; s++) {
        const float4 p = *(const float4*)(
            g_po + ((size_t)s * B_ * LQ_ + row) * PD_ + c4);
        o.x += p.x * w[s]; o.y += p.y * w[s];
        o.z += p.z * w[s]; o.w += p.w * w[s];
    }
    o.x *= inv; o.y *= inv; o.z *= inv; o.w *= inv;
    *(float4*)(out + (size_t)row * PD_ + c4) = o;
}

// ---------------------------------------------------------------------------
extern "C" void kernel_launch(void* const* d_in, const int* in_sizes, int n_in,
                              void* d_out, int out_size)
{
    const float* x  = (const float*)d_in[0];
    const float* y  = (const float*)d_in[1];
    const float* Wq = (const float*)d_in[2];
    const float* bq = (const float*)d_in[3];
    const float* Wk = (const float*)d_in[4];
    const float* bk = (const float*)d_in[5];
    const float* Wv = (const float*)d_in[6];
    const float* bv = (const float*)d_in[7];
    const int* maskp = (const int*)d_in[8];
    float* out = (float*)d_out;

    (void)in_sizes; (void)n_in; (void)out_size;

    cudaFuncSetAttribute(attn_kernel,
                         cudaFuncAttributeMaxDynamicSharedMemorySize, SMEM_BYTES);

    // total threads: 2*NX4 (x,y) + 98304 (W^T) = 4,292,608 -> 16768 blocks
    cvt_kernel<<<16768, 256>>>(x, y, Wq, Wk, Wv);

    dim3 pg(128, 3);
    proj_kernel<<<pg, 128>>>(bq, bk, bv);

    dim3 ag(LQ_ / BQ, B_, NSPLIT);
    attn_kernel<<<ag, 128, SMEM_BYTES>>>(maskp);

    combine_kernel<<<(B_ * LQ_ * PD_ / 4) / 256, 256>>>(out);
}

// round 13
// speedup vs baseline: 1.9265x; 1.1953x over previous
#include <cuda_runtime.h>
#include <cuda_pipeline.h>
#include <cuda_fp16.h>
#include <math.h>
#include <stdint.h>

#define B_   4
#define LQ_  2048
#define LK_  2048
#define XS_  1024
#define PD_  128
#define NSPLIT 4

// Device-global scratch (no allocation allowed).
__device__ __half g_wth[3 * PD_ * XS_];     // [mat][n][k] = half(W^T)
__device__ __half g_qh[B_ * LQ_ * PD_];     // projected q (half)
__device__ __half g_kh[B_ * LK_ * PD_];     // projected k (half)
__device__ __half g_vt[B_ * PD_ * LK_];     // projected v, TRANSPOSED [b][d][j]
__device__ float  g_po[NSPLIT * B_ * LQ_ * PD_];
__device__ float  g_ml[NSPLIT * B_ * LQ_ * 2];

// D += A*B, m16n8k16 f16 inputs, f32 accum. a: 4 words (8 halves), b: 2 words.
__device__ __forceinline__ void mma_f16(float* c, const uint32_t* a, const uint32_t* b) {
    asm volatile(
        "mma.sync.aligned.m16n8k16.row.col.f32.f16.f16.f32 "
        "{%0,%1,%2,%3}, {%4,%5,%6,%7}, {%8,%9}, {%0,%1,%2,%3};\n"
        : "+f"(c[0]), "+f"(c[1]), "+f"(c[2]), "+f"(c[3])
        : "r"(a[0]), "r"(a[1]), "r"(a[2]), "r"(a[3]), "r"(b[0]), "r"(b[1]));
}

__device__ __forceinline__ uint32_t h2u(__half2 h) {
    return *reinterpret_cast<uint32_t*>(&h);
}

// ---------------------------------------------------------------------------
// wcvt_kernel: one-time W fp32 -> half, transposed to [mat][n][k].
// 3*128*1024/4 = 98,304 half4-groups -> 384 blocks x 256 threads.
// ---------------------------------------------------------------------------
__global__ __launch_bounds__(256) void wcvt_kernel(
    const float* __restrict__ Wq, const float* __restrict__ Wk,
    const float* __restrict__ Wv)
{
    const int i = blockIdx.x * 256 + threadIdx.x;    // 0..98303
    const int mat = i / (PD_ * XS_ / 4);
    const int r = i % (PD_ * XS_ / 4);
    const int n = r >> 8;              // 0..127
    const int k4 = (r & 255) * 4;      // 0..1020
    const float* W = (mat == 0) ? Wq : ((mat == 1) ? Wk : Wv);
    const float f0 = W[(size_t)(k4 + 0) * PD_ + n];
    const float f1 = W[(size_t)(k4 + 1) * PD_ + n];
    const float f2 = W[(size_t)(k4 + 2) * PD_ + n];
    const float f3 = W[(size_t)(k4 + 3) * PD_ + n];
    __half2* dst = (__half2*)(g_wth + ((size_t)mat * PD_ + n) * XS_ + k4);
    dst[0] = __floats2half2_rn(f0, f1);
    dst[1] = __floats2half2_rn(f2, f3);
}

// ---------------------------------------------------------------------------
// Projection GEMM (fp16 m16n8k16), fused fp32->fp16 of A:
//   C[8192,128] = A[8192,1024]@W[1024,128]+b
// CTA tile 64x128, grid (128,3). 128 thr = 4 warps (2m x 2n), warp 32x64.
// A read as fp32 via register-staged LDG, packed to half, STS into a SINGLE
// As buffer bracketed by two syncthreads (proven R10 structure); B (half W^T)
// double-buffered cp.async. BK=32. Epilogue: +bias fp32, round to half;
// V written transposed [b][d][j].
// ---------------------------------------------------------------------------
#define PAW 20
#define PBW 20

__global__ __launch_bounds__(128) void proj_kernel(
    const float* __restrict__ x, const float* __restrict__ y,
    const float* __restrict__ bq, const float* __restrict__ bk,
    const float* __restrict__ bv)
{
    __shared__ uint32_t As[64 * PAW];        // [m][k-words], single buffer
    __shared__ uint32_t Bs[2 * 128 * PBW];   // [buf][n][k-words]

    const int mat = blockIdx.y;
    const float* A = (mat == 0) ? x : y;
    const float* bias = (mat == 0) ? bq : ((mat == 1) ? bk : bv);
    const __half* Bw = g_wth + (size_t)mat * PD_ * XS_;
    const int row0 = blockIdx.x * 64;

    const int tid  = threadIdx.x;
    const int wid  = tid >> 5;
    const int lane = tid & 31;
    const int lr = lane >> 2, lc = lane & 3;
    const int rw = (wid & 1) * 32;
    const int cw = (wid >> 1) * 64;

    // A-slot mapping: i in {0,1}, g = tid + i*128, m = g>>2, c4 = g&3
    // -> words [m*PAW + c4*4 .. +3] <- fp32 A[row0+m][kc + c4*8 .. +7]
    // prologue: stage A(0) to regs, launch B(0)
    float4 rA[4];
    #pragma unroll
    for (int i = 0; i < 2; i++) {
        const int g = tid + i * 128;
        const int m = g >> 2, c4 = g & 3;
        rA[2 * i]     = *(const float4*)(A + (size_t)(row0 + m) * XS_ + c4 * 8);
        rA[2 * i + 1] = *(const float4*)(A + (size_t)(row0 + m) * XS_ + c4 * 8 + 4);
    }
    #pragma unroll
    for (int i = 0; i < 4; i++) {
        const int g = tid + i * 128;
        const int n = g >> 2, cq = g & 3;
        __pipeline_memcpy_async(&Bs[n * PBW + cq * 4],
                                Bw + (size_t)n * XS_ + cq * 8, 16);
    }
    __pipeline_commit();

    float acc[2][8][4];
    #pragma unroll
    for (int mf = 0; mf < 2; mf++)
        #pragma unroll
        for (int nf = 0; nf < 8; nf++)
            #pragma unroll
            for (int r = 0; r < 4; r++) acc[mf][nf][r] = 0.0f;

    for (int c = 0; c < 32; c++) {
        const int buf = c & 1;
        __pipeline_wait_prior(0);   // B(c) landed
        __syncthreads();            // all warps done reading As(c-1)/Bs(other buf)

        // Store A(c): pack fp32 regs -> half2 words -> one STS.128 per slot
        #pragma unroll
        for (int i = 0; i < 2; i++) {
            const int g = tid + i * 128;
            const int m = g >> 2, c4 = g & 3;
            uint4 w;
            w.x = h2u(__floats2half2_rn(rA[2*i].x,   rA[2*i].y));
            w.y = h2u(__floats2half2_rn(rA[2*i].z,   rA[2*i].w));
            w.z = h2u(__floats2half2_rn(rA[2*i+1].x, rA[2*i+1].y));
            w.w = h2u(__floats2half2_rn(rA[2*i+1].z, rA[2*i+1].w));
            *(uint4*)&As[m * PAW + c4 * 4] = w;
        }
        __syncthreads();            // As(c) visible

        if (c < 31) {
            const int kc = (c + 1) * 32;
            #pragma unroll
            for (int i = 0; i < 2; i++) {
                const int g = tid + i * 128;
                const int m = g >> 2, c4 = g & 3;
                rA[2 * i]     = *(const float4*)(A + (size_t)(row0 + m) * XS_ + kc + c4 * 8);
                rA[2 * i + 1] = *(const float4*)(A + (size_t)(row0 + m) * XS_ + kc + c4 * 8 + 4);
            }
            const int nb = (c + 1) & 1;
            #pragma unroll
            for (int i = 0; i < 4; i++) {
                const int g = tid + i * 128;
                const int n = g >> 2, cq = g & 3;
                __pipeline_memcpy_async(&Bs[nb * 128 * PBW + n * PBW + cq * 4],
                                        Bw + (size_t)n * XS_ + kc + cq * 8, 16);
            }
            __pipeline_commit();
        }

        const uint32_t* Bb = Bs + buf * 128 * PBW;
        #pragma unroll
        for (int kf = 0; kf < 2; kf++) {
            const int kw = kf * 8;
            uint32_t a[2][4];
            #pragma unroll
            for (int mf = 0; mf < 2; mf++) {
                const int r = rw + mf * 16 + lr;
                a[mf][0] = As[r * PAW + kw + lc];
                a[mf][1] = As[(r + 8) * PAW + kw + lc];
                a[mf][2] = As[r * PAW + kw + lc + 4];
                a[mf][3] = As[(r + 8) * PAW + kw + lc + 4];
            }
            #pragma unroll
            for (int nf = 0; nf < 8; nf++) {
                uint32_t b[2];
                const int col = cw + nf * 8 + lr;
                b[0] = Bb[col * PBW + kw + lc];
                b[1] = Bb[col * PBW + kw + lc + 4];
                mma_f16(acc[0][nf], a[0], b);
                mma_f16(acc[1][nf], a[1], b);
            }
        }
    }

    // Epilogue: +bias, round to half.  Q/K natural layout; V transposed [b][d][j].
    #pragma unroll
    for (int mf = 0; mf < 2; mf++) {
        #pragma unroll
        for (int nf = 0; nf < 8; nf++) {
            const int row = row0 + rw + mf * 16 + lr;
            const int col = cw + nf * 8 + 2 * lc;
            const float2 bb = *(const float2*)(bias + col);
            const float v00 = acc[mf][nf][0] + bb.x;
            const float v01 = acc[mf][nf][1] + bb.y;
            const float v10 = acc[mf][nf][2] + bb.x;
            const float v11 = acc[mf][nf][3] + bb.y;
            if (mat < 2) {
                __half* C = (mat == 0) ? g_qh : g_kh;
                *(__half2*)(C + (size_t)row * PD_ + col) = __floats2half2_rn(v00, v01);
                *(__half2*)(C + (size_t)(row + 8) * PD_ + col) = __floats2half2_rn(v10, v11);
            } else {
                const int bi = row >> 11, j = row & 2047;   // row+8 stays same b
                g_vt[((size_t)bi * PD_ + col) * LK_ + j]         = __float2half_rn(v00);
                g_vt[((size_t)bi * PD_ + col + 1) * LK_ + j]     = __float2half_rn(v01);
                g_vt[((size_t)bi * PD_ + col) * LK_ + j + 8]     = __float2half_rn(v10);
                g_vt[((size_t)bi * PD_ + col + 1) * LK_ + j + 8] = __float2half_rn(v11);
            }
        }
    }
}

// ---------------------------------------------------------------------------
// Flash attention (fp16 m16n8k16), split-KV x4, post-softmax triu(k=1) mask.
// grid (32, 4, 4), 128 thr = 4 warps x 16 rows.  K now SINGLE-buffered
// (prefetch of K(t+1) issued after QK(t) behind a syncthreads; lands during
// softmax+PV), V double-buffered.  smem 51,712 B -> 4 CTAs/SM: grid 512 fits
// a single wave (592 slots) and gives 4 warps/SMSP.
// ---------------------------------------------------------------------------
#define BQ  64
#define BKT 32
#define NT  (LK_ / BKT / NSPLIT)   // 16 tiles per split
#define QWP 68
#define KWP 68
#define VWP 20
#define PWP 20
#define SQ_ 0
#define SK_ (64 * QWP)                 // 4352
#define SV_ (SK_ + 32 * KWP)           // 6528  (K single buffer)
#define SP_ (SV_ + 2 * 128 * VWP)      // 11648
#define SMEM_WORDS (SP_ + 64 * PWP)    // 12928
#define SMEM_BYTES (SMEM_WORDS * 4)    // 51,712

__global__ __launch_bounds__(128, 4) void attn_kernel(const int* __restrict__ maskp)
{
    extern __shared__ uint32_t smw[];
    uint32_t* Qw = smw + SQ_;    // [r][d-words] pitch 68
    uint32_t* Kw = smw + SK_;    // [j][d-words] pitch 68, single buffer
    uint32_t* Vw = smw + SV_;    // buf*[d][j-words] pitch 20
    uint32_t* Pw = smw + SP_;    // [r][j-words] pitch 20

    const int b = blockIdx.y;
    const int qbase = blockIdx.x * BQ;
    const int split = blockIdx.z;
    const int kstart = split * (LK_ / NSPLIT);

    const __half* Qg = g_qh + ((size_t)b * LQ_ + qbase) * PD_;
    const __half* Kg = g_kh + (size_t)b * LK_ * PD_;
    const __half* Vg = g_vt + (size_t)b * PD_ * LK_;   // [d][j]

    const int tid  = threadIdx.x;
    const int wid  = tid >> 5;
    const int lane = tid & 31;
    const int lr = lane >> 2, lc = lane & 3;
    const int r0w = wid * 16;
    const int msk = *maskp;
    const float SCALE = 0.0883883476483184f;  // 1/sqrt(128)

    // Prologue: Q (8/thr), K tile 0 (4/thr), V tile 0 (4/thr) — one group
    #pragma unroll
    for (int i = 0; i < 8; i++) {
        const int g = tid + i * 128;
        const int r = g >> 4, cq = g & 15;
        __pipeline_memcpy_async(&Qw[r * QWP + cq * 4],
                                Qg + (size_t)r * PD_ + cq * 8, 16);
    }
    #pragma unroll
    for (int i = 0; i < 4; i++) {
        const int g = tid + i * 128;
        const int r = g >> 4, cq = g & 15;
        __pipeline_memcpy_async(&Kw[r * KWP + cq * 4],
                                Kg + (size_t)(kstart + r) * PD_ + cq * 8, 16);
    }
    #pragma unroll
    for (int i = 0; i < 4; i++) {
        const int g = tid + i * 128;
        const int d = g >> 2, cq = g & 3;
        __pipeline_memcpy_async(&Vw[d * VWP + cq * 4],
                                Vg + (size_t)d * LK_ + kstart + cq * 8, 16);
    }
    __pipeline_commit();

    float oacc[16][4];
    #pragma unroll
    for (int nf = 0; nf < 16; nf++)
        #pragma unroll
        for (int r = 0; r < 4; r++) oacc[nf][r] = 0.0f;
    float m_run[2] = {-1e30f, -1e30f};
    float l_run[2] = {0.0f, 0.0f};

    for (int t = 0; t < NT; t++) {
        const int kbase = kstart + t * BKT;
        const uint32_t* Vb = Vw + (t & 1) * 128 * VWP;

        __pipeline_wait_prior(0);   // K(t) and V(t) landed
        __syncthreads();            // all warps past prior-tile reads

        // Prefetch V(t+1) into the other V buffer now.
        if (t + 1 < NT) {
            uint32_t* Vn = Vw + ((t + 1) & 1) * 128 * VWP;
            #pragma unroll
            for (int i = 0; i < 4; i++) {
                const int g = tid + i * 128;
                const int d = g >> 2, cq = g & 3;
                __pipeline_memcpy_async(&Vn[d * VWP + cq * 4],
                                        Vg + (size_t)d * LK_ + kbase + BKT + cq * 8, 16);
            }
            __pipeline_commit();
        }

        // ---- S = Q @ K^T (warp: 16 rows x 32 cols; 8 kf x 4 nf = 32 MMA) ----
        float sacc[4][4];
        #pragma unroll
        for (int nf = 0; nf < 4; nf++)
            #pragma unroll
            for (int r = 0; r < 4; r++) sacc[nf][r] = 0.0f;

        #pragma unroll 4
        for (int kf = 0; kf < 8; kf++) {
            const int kw = kf * 8;
            uint32_t a[4];
            a[0] = Qw[(r0w + lr) * QWP + kw + lc];
            a[1] = Qw[(r0w + lr + 8) * QWP + kw + lc];
            a[2] = Qw[(r0w + lr) * QWP + kw + lc + 4];
            a[3] = Qw[(r0w + lr + 8) * QWP + kw + lc + 4];
            #pragma unroll
            for (int nf = 0; nf < 4; nf++) {
                uint32_t bfr[2];
                bfr[0] = Kw[(nf * 8 + lr) * KWP + kw + lc];
                bfr[1] = Kw[(nf * 8 + lr) * KWP + kw + lc + 4];
                mma_f16(sacc[nf], a, bfr);
            }
        }

        __syncthreads();            // all warps done reading Kw
        // Prefetch K(t+1) into the single K buffer; lands by next wait_prior.
        if (t + 1 < NT) {
            #pragma unroll
            for (int i = 0; i < 4; i++) {
                const int g = tid + i * 128;
                const int r = g >> 4, cq = g & 15;
                __pipeline_memcpy_async(&Kw[r * KWP + cq * 4],
                                        Kg + (size_t)(kbase + BKT + r) * PD_ + cq * 8, 16);
            }
            __pipeline_commit();
        }

        // ---- online softmax (warp-local; rows lr, lr+8) ----
        #pragma unroll
        for (int nf = 0; nf < 4; nf++)
            #pragma unroll
            for (int r = 0; r < 4; r++) sacc[nf][r] *= SCALE;

        float m_t[2] = {-1e30f, -1e30f};
        #pragma unroll
        for (int nf = 0; nf < 4; nf++) {
            m_t[0] = fmaxf(m_t[0], fmaxf(sacc[nf][0], sacc[nf][1]));
            m_t[1] = fmaxf(m_t[1], fmaxf(sacc[nf][2], sacc[nf][3]));
        }
        #pragma unroll
        for (int off = 2; off >= 1; off >>= 1) {
            m_t[0] = fmaxf(m_t[0], __shfl_xor_sync(0xffffffffu, m_t[0], off));
            m_t[1] = fmaxf(m_t[1], __shfl_xor_sync(0xffffffffu, m_t[1], off));
        }
        float m_new[2], corr[2], lp[2] = {0.0f, 0.0f};
        #pragma unroll
        for (int r = 0; r < 2; r++) {
            m_new[r] = fmaxf(m_run[r], m_t[r]);
            corr[r] = __expf(m_run[r] - m_new[r]);
        }
        #pragma unroll
        for (int nf = 0; nf < 4; nf++) {
            #pragma unroll
            for (int r = 0; r < 4; r++) {
                const float e = __expf(sacc[nf][r] - m_new[r >> 1]);
                sacc[nf][r] = e;
                lp[r >> 1] += e;
            }
        }
        #pragma unroll
        for (int off = 2; off >= 1; off >>= 1) {
            lp[0] += __shfl_xor_sync(0xffffffffu, lp[0], off);
            lp[1] += __shfl_xor_sync(0xffffffffu, lp[1], off);
        }
        #pragma unroll
        for (int r = 0; r < 2; r++) {
            l_run[r] = l_run[r] * corr[r] + lp[r];
            m_run[r] = m_new[r];
        }
        #pragma unroll
        for (int nf = 0; nf < 16; nf++) {
            oacc[nf][0] *= corr[0]; oacc[nf][1] *= corr[0];
            oacc[nf][2] *= corr[1]; oacc[nf][3] *= corr[1];
        }

        // Tile fully below/at diagonal for all rows of this CTA -> P == 0
        const bool pv_skip = msk && (kbase + BKT - 1 <= qbase);
        if (!pv_skip) {
            // masked P -> smem as packed half2 (warp-private rows)
            const int rowg0 = qbase + r0w + lr;
            const int rowg1 = rowg0 + 8;
            #pragma unroll
            for (int nf = 0; nf < 4; nf++) {
                const int col = nf * 8 + 2 * lc;
                const int kidx = kbase + col;
                const bool z00 = msk && (kidx     <= rowg0);
                const bool z01 = msk && (kidx + 1 <= rowg0);
                const bool z10 = msk && (kidx     <= rowg1);
                const bool z11 = msk && (kidx + 1 <= rowg1);
                Pw[(r0w + lr) * PWP + nf * 4 + lc] =
                    h2u(__floats2half2_rn(z00 ? 0.0f : sacc[nf][0],
                                          z01 ? 0.0f : sacc[nf][1]));
                Pw[(r0w + lr + 8) * PWP + nf * 4 + lc] =
                    h2u(__floats2half2_rn(z10 ? 0.0f : sacc[nf][2],
                                          z11 ? 0.0f : sacc[nf][3]));
            }
            __syncwarp();

            // ---- O += P @ V (2 jf x 16 nf = 32 MMA) ----
            #pragma unroll
            for (int jf = 0; jf < 2; jf++) {
                const int jw = jf * 8;
                uint32_t pa[4];
                pa[0] = Pw[(r0w + lr) * PWP + jw + lc];
                pa[1] = Pw[(r0w + lr + 8) * PWP + jw + lc];
                pa[2] = Pw[(r0w + lr) * PWP + jw + lc + 4];
                pa[3] = Pw[(r0w + lr + 8) * PWP + jw + lc + 4];
                #pragma unroll
                for (int nf = 0; nf < 16; nf++) {
                    uint32_t vb[2];
                    vb[0] = Vb[(nf * 8 + lr) * VWP + jw + lc];
                    vb[1] = Vb[(nf * 8 + lr) * VWP + jw + lc + 4];
                    mma_f16(oacc[nf], pa, vb);
                }
            }
            __syncwarp();
        }
    }

    // Epilogue: unnormalized partial O + (m, l)
    float* Pog = g_po + ((size_t)(split * B_ + b) * LQ_ + qbase) * PD_;
    #pragma unroll
    for (int nf = 0; nf < 16; nf++) {
        const int row = r0w + lr;
        const int col = nf * 8 + 2 * lc;
        *(float2*)(Pog + (size_t)row * PD_ + col) =
            make_float2(oacc[nf][0], oacc[nf][1]);
        *(float2*)(Pog + (size_t)(row + 8) * PD_ + col) =
            make_float2(oacc[nf][2], oacc[nf][3]);
    }
    if (lc == 0) {
        float* mlg = g_ml + ((size_t)(split * B_ + b) * LQ_ + qbase) * 2;
        *(float2*)(mlg + (size_t)(r0w + lr) * 2)     = make_float2(m_run[0], l_run[0]);
        *(float2*)(mlg + (size_t)(r0w + lr + 8) * 2) = make_float2(m_run[1], l_run[1]);
    }
}

// ---------------------------------------------------------------------------
// Split-KV combine over NSPLIT=4 partials.
// ---------------------------------------------------------------------------
__global__ __launch_bounds__(256) void combine_kernel(float* __restrict__ out)
{
    const int idx = blockIdx.x * 256 + threadIdx.x;   // one float4 of out
    const int row = idx >> 5;                          // global (b*LQ + q)
    const int c4 = (idx & 31) * 4;

    float2 ml[NSPLIT];
    #pragma unroll
    for (int s = 0; s < NSPLIT; s++)
        ml[s] = *(const float2*)(g_ml + ((size_t)s * B_ * LQ_ + row) * 2);

    float m = ml[0].x;
    #pragma unroll
    for (int s = 1; s < NSPLIT; s++) m = fmaxf(m, ml[s].x);

    float w[NSPLIT], denom = 0.0f;
    #pragma unroll
    for (int s = 0; s < NSPLIT; s++) {
        w[s] = __expf(ml[s].x - m);
        denom += ml[s].y * w[s];
    }
    const float inv = 1.0f / denom;

    float4 o = make_float4(0.0f, 0.0f, 0.0f, 0.0f);
    #pragma unroll
    for (int s = 0; s < NSPLIT; s++) {
        const float4 p = *(const float4*)(
            g_po + ((size_t)s * B_ * LQ_ + row) * PD_ + c4);
        o.x += p.x * w[s]; o.y += p.y * w[s];
        o.z += p.z * w[s]; o.w += p.w * w[s];
    }
    o.x *= inv; o.y *= inv; o.z *= inv; o.w *= inv;
    *(float4*)(out + (size_t)row * PD_ + c4) = o;
}

// ---------------------------------------------------------------------------
extern "C" void kernel_launch(void* const* d_in, const int* in_sizes, int n_in,
                              void* d_out, int out_size)
{
    const float* x  = (const float*)d_in[0];
    const float* y  = (const float*)d_in[1];
    const float* Wq = (const float*)d_in[2];
    const float* bq = (const float*)d_in[3];
    const float* Wk = (const float*)d_in[4];
    const float* bk = (const float*)d_in[5];
    const float* Wv = (const float*)d_in[6];
    const float* bv = (const float*)d_in[7];
    const int* maskp = (const int*)d_in[8];
    float* out = (float*)d_out;

    (void)in_sizes; (void)n_in; (void)out_size;

    cudaFuncSetAttribute(attn_kernel,
                         cudaFuncAttributeMaxDynamicSharedMemorySize, SMEM_BYTES);

    wcvt_kernel<<<384, 256>>>(Wq, Wk, Wv);

    dim3 pg(128, 3);
    proj_kernel<<<pg, 128>>>(x, y, bq, bk, bv);

    dim3 ag(LQ_ / BQ, B_, NSPLIT);
    attn_kernel<<<ag, 128, SMEM_BYTES>>>(maskp);

    combine_kernel<<<(B_ * LQ_ * PD_ / 4) / 256, 256>>>(out);
}